// round 4
// baseline (speedup 1.0000x reference)
#include <cuda_runtime.h>
#include <cstdint>
#include <math.h>

typedef unsigned long long ull;

#define NN 512
#define DD 64
#define BB 8
#define KSEL 256
#define XP 258   // padded pitch for transposed x tile (floats)

// Scratch (static __device__ arrays: no allocation allowed)
__device__ float g_L[(size_t)BB * NN * NN];   // logits  8 MB
__device__ float g_h[(size_t)BB * NN * DD];   // h after selu
__device__ float g_s[(size_t)BB * NN];        // sigmoid scores

// Fast accurate-enough tanh: ex2.approx + rcp.approx with one Newton step.
// tanh(|x|) = (1-t)/(1+t), t = 2^(-2|x|*log2e).  abs err ~1e-7.
__device__ __forceinline__ float fast_tanh(float x) {
    float ax = fabsf(x);
    float t;
    asm("ex2.approx.f32 %0, %1;" : "=f"(t) : "f"(ax * -2.8853900817779268f));
    float u = 1.0f + t;
    float r;
    asm("rcp.approx.f32 %0, %1;" : "=f"(r) : "f"(u));
    r = r * fmaf(-u, r, 2.0f);          // Newton refine
    float v = (1.0f - t) * r;           // in [0,1)
    return copysignf(v, x);
}

// ---------------------------------------------------------------------------
// Kernel 1: logits[b][i][j] = sum_o v[o]*tanh( sum_d x[b,i,d]*W[d,o]*x[b,j,d] + b[o] )
// Symmetric: CTA (b,i) computes k=(j-i) mod 512 in [0,255] (+256 if i<256),
// writes both [i][j] and [j][i]. Inner GEMM uses packed fma.rn.f32x2.
// R1-proven mainloop structure (unroll 4, LDS.64 broadcasts, low regs).
// ---------------------------------------------------------------------------
__global__ __launch_bounds__(256, 2) void k1_logits(
    const float* __restrict__ x, const float* __restrict__ attw,
    const float* __restrict__ attb, const float* __restrict__ attv)
{
    extern __shared__ float smem[];
    float* xT  = smem;                         // [64][XP], jloc 0..256 used
    ull*   Wp2 = (ull*)(smem + 64 * XP);       // [64][64] lane-duplicated W'
    float* red = (float*)(Wp2 + 64 * 64);      // [8][256]
    float* vv  = red + 8 * 256;                // [64]
    float* bbv = vv + 64;                      // [64]

    const int i = blockIdx.x, b = blockIdx.y;
    const int tid = threadIdx.x;
    const int jg = tid & 31, og = tid >> 5;

    // Load x window (rows i..i+256 mod 512) transposed into smem
    for (int idx = tid; idx < 257 * 64; idx += 256) {
        int r = idx >> 6, d = idx & 63;
        int g = (i + r) & (NN - 1);
        xT[d * XP + r] = x[((size_t)b * NN + g) * DD + d];
    }
    if (tid < 64) { vv[tid] = attv[tid]; bbv[tid] = attb[tid]; }
    __syncthreads();

    // W'[d][o] = x[b,i,d] * W[d,o], duplicated into both f32x2 lanes
    for (int idx = tid; idx < 64 * 64; idx += 256) {
        int d = idx >> 6;
        float w = xT[d * XP] * attw[idx];
        ull wd; asm("mov.b64 %0,{%1,%1};" : "=l"(wd) : "f"(w));
        Wp2[idx] = wd;
    }
    __syncthreads();

    // Register tile: 8 j (4 pairs) x 8 o per thread; 256 threads cover 256 j x 64 o
    // Accumulators start at the (lane-duplicated) bias -> epilogue tanh is direct.
    ull acc[4][8];
    #pragma unroll
    for (int c = 0; c < 8; c++) {
        float bo = bbv[og * 8 + c];
        ull bd; asm("mov.b64 %0,{%1,%1};" : "=l"(bd) : "f"(bo));
        #pragma unroll
        for (int r = 0; r < 4; r++) acc[r][c] = bd;
    }

    #pragma unroll 4
    for (int d = 0; d < 64; d++) {
        ull xp[4];
        #pragma unroll
        for (int r = 0; r < 4; r++)
            xp[r] = *(const ull*)&xT[d * XP + 2 * jg + 64 * r];
        ull wv[8];
        #pragma unroll
        for (int c = 0; c < 8; c++)
            wv[c] = Wp2[d * 64 + og * 8 + c];
        #pragma unroll
        for (int r = 0; r < 4; r++)
            #pragma unroll
            for (int c = 0; c < 8; c++)
                asm("fma.rn.f32x2 %0, %1, %2, %0;"
                    : "+l"(acc[r][c]) : "l"(xp[r]), "l"(wv[c]));
    }

    // Epilogue: tanh + reduce over o (v-weighted), partial per og group
    #pragma unroll
    for (int r = 0; r < 4; r++) {
        float plo = 0.f, phi = 0.f;
        #pragma unroll
        for (int c = 0; c < 8; c++) {
            int o = og * 8 + c;
            float lo, hi;
            asm("mov.b64 {%0,%1}, %2;" : "=f"(lo), "=f"(hi) : "l"(acc[r][c]));
            plo += vv[o] * fast_tanh(lo);
            phi += vv[o] * fast_tanh(hi);
        }
        int jloc = 2 * jg + 64 * r;
        red[og * 256 + jloc]     = plo;
        red[og * 256 + jloc + 1] = phi;
    }
    __syncthreads();
    {
        float s = 0.f;
        #pragma unroll
        for (int g = 0; g < 8; g++) s += red[g * 256 + tid];
        int jglob = (i + tid) & (NN - 1);
        g_L[((size_t)b * NN + i) * NN + jglob] = s;
        g_L[((size_t)b * NN + jglob) * NN + i] = s;   // symmetric mirror
    }

    // Tail k=256: single writer (i<256) for determinism
    if (i < 256) {
        __syncthreads();
        if (tid < 64) {
            float q = bbv[tid];
            #pragma unroll 8
            for (int d = 0; d < 64; d++)
                q += (xT[d * XP] * attw[d * 64 + tid]) * xT[d * XP + 256];
            red[tid] = vv[tid] * fast_tanh(q);
        }
        __syncthreads();
        if (tid == 0) {
            float s = 0.f;
            for (int o = 0; o < 64; o++) s += red[o];
            int jglob = (i + 256) & (NN - 1);
            g_L[((size_t)b * NN + i) * NN + jglob] = s;
            g_L[((size_t)b * NN + jglob) * NN + i] = s;
        }
    }
}

// ---------------------------------------------------------------------------
// Kernel 2 (tiled, 512 threads): CTA = (itile of 32 rows, b). Smem holds the
// 32x512 logit tile and the full x_b. Softmax, agg GEMM, h/BN/selu, scores.
// ---------------------------------------------------------------------------
#define ITILE 32
__global__ __launch_bounds__(512, 1) void k2_head(
    const float* __restrict__ x,
    const float* __restrict__ pwa_w, const float* __restrict__ pwa_b,
    const float* __restrict__ pwo_w, const float* __restrict__ pwo_b,
    const float* __restrict__ gamma, const float* __restrict__ beta,
    const float* __restrict__ poolw, const float* __restrict__ poolb)
{
    extern __shared__ float s2[];
    float* att = s2;                       // [32][512] (reused as hsm later)
    float* xs  = s2 + ITILE * NN;          // [512][64]
    float* agg = xs + NN * DD;             // [32][64]
    float* inv = agg + ITILE * DD;         // [32]
    float* hsm = att;                      // alias (att dead after agg)

    const int itile = blockIdx.x, b = blockIdx.y;
    const int tid = threadIdx.x;
    const int wid = tid >> 5, lane = tid & 31;

    // Load logit tile + full x_b into smem (float4, coalesced)
    {
        const float4* Ls = (const float4*)(g_L + ((size_t)b * NN + itile * ITILE) * NN);
        float4* Ld = (float4*)att;
        for (int idx = tid; idx < ITILE * NN / 4; idx += 512) Ld[idx] = Ls[idx];
        const float4* Xs = (const float4*)(x + (size_t)b * NN * DD);
        float4* Xd = (float4*)xs;
        for (int idx = tid; idx < NN * DD / 4; idx += 512) Xd[idx] = Xs[idx];
    }
    __syncthreads();

    // Row softmax: 16 warps, 2 rows each; exp in place (unnormalized), 1/sum
    #pragma unroll
    for (int rr = 0; rr < 2; rr++) {
        int r = wid + rr * 16;
        float* row = att + r * NN;
        float m = -1e30f;
        #pragma unroll 4
        for (int j = lane; j < NN; j += 32) m = fmaxf(m, row[j]);
        #pragma unroll
        for (int off = 16; off; off >>= 1) m = fmaxf(m, __shfl_xor_sync(~0u, m, off));
        float ssum = 0.f;
        #pragma unroll 4
        for (int j = lane; j < NN; j += 32) {
            float e = __expf(row[j] - m);
            row[j] = e;
            ssum += e;
        }
        #pragma unroll
        for (int off = 16; off; off >>= 1) ssum += __shfl_xor_sync(~0u, ssum, off);
        if (lane == 0) inv[r] = 1.0f / ssum;
    }
    __syncthreads();

    // agg[i][d] = inv[i] * sum_j att[i][j] * xs[j][d]; 8 groups x 4 rows
    const int d = tid & 63, ig = tid >> 6;
    float acc[4] = {0, 0, 0, 0};
    for (int j = 0; j < NN; j += 4) {
        float x0 = xs[(j + 0) * DD + d];
        float x1 = xs[(j + 1) * DD + d];
        float x2 = xs[(j + 2) * DD + d];
        float x3 = xs[(j + 3) * DD + d];
        #pragma unroll
        for (int s = 0; s < 4; s++) {
            float4 a = *(const float4*)&att[(ig * 4 + s) * NN + j];
            acc[s] = fmaf(a.x, x0, acc[s]);
            acc[s] = fmaf(a.y, x1, acc[s]);
            acc[s] = fmaf(a.z, x2, acc[s]);
            acc[s] = fmaf(a.w, x3, acc[s]);
        }
    }
    __syncthreads();   // att reads done before hsm overwrites it
    #pragma unroll
    for (int s = 0; s < 4; s++)
        agg[(ig * 4 + s) * DD + d] = acc[s] * inv[ig * 4 + s];
    __syncthreads();

    // h = agg@pwa + x_i@pwo + biases, BN(eval) scale, selu  (o = tid&63)
    {
        const int o = d;
        float hv[4];
        float pb = pwa_b[o] + pwo_b[o];
        #pragma unroll
        for (int s = 0; s < 4; s++) hv[s] = pb;
        #pragma unroll 8
        for (int dd = 0; dd < 64; dd++) {
            float wa = __ldg(&pwa_w[dd * 64 + o]);
            float wo = __ldg(&pwo_w[dd * 64 + o]);
            #pragma unroll
            for (int s = 0; s < 4; s++) {
                int i = ig * 4 + s;
                hv[s] = fmaf(agg[i * DD + dd], wa, hv[s]);
                hv[s] = fmaf(xs[(itile * ITILE + i) * DD + dd], wo, hv[s]);
            }
        }
        const float BNS = 0.99999500003749969f;  // 1/sqrt(1+1e-5)
        float gam = gamma[o] * BNS, bet = beta[o];
        const float SC = 1.0507009873554804934193349852946f;
        const float AL = 1.6732632423543772848170429916717f;
        #pragma unroll
        for (int s = 0; s < 4; s++) {
            float h = fmaf(hv[s], gam, bet);
            h = h > 0.f ? SC * h : SC * AL * expm1f(h);
            hsm[(ig * 4 + s) * DD + o] = h;
        }
    }
    __syncthreads();

    // Pool scores (accurate exp for rank stability) + write h
    if (tid < ITILE) {
        float z = poolb[0];
        #pragma unroll 8
        for (int oo = 0; oo < 64; oo++) z = fmaf(hsm[tid * 64 + oo], poolw[oo], z);
        g_s[(size_t)b * NN + itile * ITILE + tid] = 1.0f / (1.0f + expf(-z));
    }
    {
        float4* gh = (float4*)(g_h + ((size_t)b * NN + itile * ITILE) * DD);
        const float4* hs = (const float4*)hsm;
        for (int idx = tid; idx < ITILE * DD / 4; idx += 512) gh[idx] = hs[idx];
    }
}

// ---------------------------------------------------------------------------
// Kernel 3: per batch, descending top-256 (stable: lower idx wins ties),
// gather out[b][r] = h[b][idx_r] * score[idx_r]
// ---------------------------------------------------------------------------
__global__ __launch_bounds__(512) void k3_topk(float* __restrict__ out)
{
    __shared__ ull keys[NN];
    const int b = blockIdx.x, tid = threadIdx.x;
    {
        float sc = g_s[(size_t)b * NN + tid];
        keys[tid] = ((ull)__float_as_uint(sc) << 32) | (ull)(unsigned)(511 - tid);
    }
    __syncthreads();
    for (int k = 2; k <= NN; k <<= 1) {
        for (int j = k >> 1; j > 0; j >>= 1) {
            int ixj = tid ^ j;
            if (ixj > tid) {
                ull a = keys[tid], c = keys[ixj];
                bool asc = (tid & k) == 0;
                if ((a > c) == asc) { keys[tid] = c; keys[ixj] = a; }
            }
            __syncthreads();
        }
    }
    const int r = tid >> 1, ho = (tid & 1) * 32;
    ull key = keys[(NN - 1) - r];
    float sc = __uint_as_float((unsigned)(key >> 32));
    int idx = 511 - (int)(key & 0xffffffffu);
    const float* hr = &g_h[((size_t)b * NN + idx) * DD];
    float* orow = &out[((size_t)b * KSEL + r) * DD];
    #pragma unroll
    for (int c = 0; c < 32; c++)
        orow[ho + c] = hr[ho + c] * sc;
}

// ---------------------------------------------------------------------------
extern "C" void kernel_launch(void* const* d_in, const int* in_sizes, int n_in,
                              void* d_out, int out_size)
{
    (void)in_sizes; (void)n_in; (void)out_size;
    const float* x      = (const float*)d_in[0];
    const float* attw   = (const float*)d_in[1];
    const float* attb   = (const float*)d_in[2];
    const float* attv   = (const float*)d_in[3];
    const float* pwa_w  = (const float*)d_in[4];
    const float* pwa_b  = (const float*)d_in[5];
    const float* pwo_w  = (const float*)d_in[6];
    const float* pwo_b  = (const float*)d_in[7];
    const float* gamma  = (const float*)d_in[8];
    const float* beta   = (const float*)d_in[9];
    const float* poolw  = (const float*)d_in[10];
    const float* poolb  = (const float*)d_in[11];

    const int SMEM1 = (64 * XP + 2 * 64 * 64 + 8 * 256 + 128) * (int)sizeof(float);
    cudaFuncSetAttribute(k1_logits, cudaFuncAttributeMaxDynamicSharedMemorySize, SMEM1);
    const int SMEM2 = (ITILE * NN + NN * DD + ITILE * DD + ITILE) * (int)sizeof(float);
    cudaFuncSetAttribute(k2_head, cudaFuncAttributeMaxDynamicSharedMemorySize, SMEM2);

    dim3 g1(NN, BB);
    k1_logits<<<g1, 256, SMEM1>>>(x, attw, attb, attv);
    dim3 g2(NN / ITILE, BB);
    k2_head<<<g2, 512, SMEM2>>>(x, pwa_w, pwa_b, pwo_w, pwo_b, gamma, beta, poolw, poolb);
    k3_topk<<<BB, NN>>>((float*)d_out);
}

// round 6
// speedup vs baseline: 1.5306x; 1.5306x over previous
#include <cuda_runtime.h>
#include <cuda_fp16.h>
#include <cstdint>
#include <math.h>

typedef unsigned long long ull;
typedef unsigned int u32;

#define NN 512
#define DD 64
#define BB 8
#define KSEL 256

// Scratch (no allocation allowed)
__device__ float g_L[(size_t)BB * NN * NN];   // logits  8 MB
__device__ float g_h[(size_t)BB * NN * DD];   // h after selu
__device__ float g_s[(size_t)BB * NN];        // sigmoid scores

// Fast tanh: ex2.approx + rcp.approx + 1 Newton step. abs err ~1e-7.
__device__ __forceinline__ float fast_tanh(float x) {
    float ax = fabsf(x), t, r;
    asm("ex2.approx.f32 %0, %1;" : "=f"(t) : "f"(ax * -2.8853900817779268f));
    float u = 1.0f + t;
    asm("rcp.approx.f32 %0, %1;" : "=f"(r) : "f"(u));
    r = r * fmaf(-u, r, 2.0f);
    return copysignf((1.0f - t) * r, x);
}

__device__ __forceinline__ u32 smem_u32(const void* p) {
    u32 a;
    asm("{ .reg .u64 t; cvta.to.shared.u64 t, %1; cvt.u32.u64 %0, t; }" : "=r"(a) : "l"(p));
    return a;
}

#define LDSM4(r0, r1, r2, r3, a) \
    asm volatile("ldmatrix.sync.aligned.m8n8.x4.shared.b16 {%0,%1,%2,%3}, [%4];" \
        : "=r"(r0), "=r"(r1), "=r"(r2), "=r"(r3) : "r"(a))

__device__ __forceinline__ void mma16816(float* c, const u32* a, u32 b0, u32 b1) {
    asm volatile(
        "mma.sync.aligned.m16n8k16.row.col.f32.f16.f16.f32 "
        "{%0,%1,%2,%3}, {%4,%5,%6,%7}, {%8,%9}, {%0,%1,%2,%3};"
        : "+f"(c[0]), "+f"(c[1]), "+f"(c[2]), "+f"(c[3])
        : "r"(a[0]), "r"(a[1]), "r"(a[2]), "r"(a[3]), "r"(b0), "r"(b1));
}

// ---------------- Kernel 1: logits via HMMA fp16 hi/lo (3-term) ----------------
// S[j][o] = sum_d A[j][d] * B[o][d],  A = x rows (i..i+255), B[o][d] = x_i[d]*W[d][o]
// logit = sum_o v[o] * tanh(S[j][o] + b[o]);  symmetric halving as before.
#define PITCH 144            // bytes per fp16 row of 64 (128B data + 16B pad)
#define OFF_XI  0
#define OFF_VV  256
#define OFF_BV  512
#define OFF_RED 768
#define OFF_AHI 1024
#define OFF_ALO (OFF_AHI + 256 * PITCH)     // +36864
#define OFF_BHI (OFF_ALO + 256 * PITCH)
#define OFF_BLO (OFF_BHI + 64 * PITCH)
#define SMEM1   (OFF_BLO + 64 * PITCH)      // 93184 bytes

__global__ __launch_bounds__(256, 2) void k1_logits(
    const float* __restrict__ x, const float* __restrict__ attw,
    const float* __restrict__ attb, const float* __restrict__ attv)
{
    extern __shared__ char smem[];
    const u32 sb = smem_u32(smem);
    const int tid = threadIdx.x, w = tid >> 5, lane = tid & 31;
    const int i = blockIdx.x, b = blockIdx.y;

    float* xi = (float*)(smem + OFF_XI);
    float* vv = (float*)(smem + OFF_VV);
    float* bv = (float*)(smem + OFF_BV);

    if (tid < 64) {
        xi[tid] = x[((size_t)b * NN + i) * DD + tid];
        vv[tid] = attv[tid];
        bv[tid] = attb[tid];
    }
    __syncthreads();

    // A fill: rows j=0..255 -> x[(i+j)&511], fp16 hi + lo residual
    const float* xb = x + (size_t)b * NN * DD;
    for (int idx = tid; idx < 256 * 32; idx += 256) {
        int r = idx >> 5, p = idx & 31;
        const float2 v = *(const float2*)(xb + (size_t)((i + r) & (NN - 1)) * DD + 2 * p);
        __half h0 = __float2half_rn(v.x), h1 = __float2half_rn(v.y);
        __half l0 = __float2half_rn(v.x - __half2float(h0));
        __half l1 = __float2half_rn(v.y - __half2float(h1));
        *(__half2*)(smem + OFF_AHI + r * PITCH + 4 * p) = __halves2half2(h0, h1);
        *(__half2*)(smem + OFF_ALO + r * PITCH + 4 * p) = __halves2half2(l0, l1);
    }
    // B fill: B[o][d] = x_i[d] * W[d][o]
    for (int idx = tid; idx < 64 * 64; idx += 256) {
        int d = idx >> 6, o = idx & 63;
        float wv2 = xi[d] * attw[idx];
        __half h = __float2half_rn(wv2);
        __half l = __float2half_rn(wv2 - __half2float(h));
        *(__half*)(smem + OFF_BHI + o * PITCH + 2 * d) = h;
        *(__half*)(smem + OFF_BLO + o * PITCH + 2 * d) = l;
    }
    __syncthreads();

    // Per-warp output block: 32 j (2 m16 tiles) x 64 o (8 n8 tiles)
    float acc[2][8][4];
    #pragma unroll
    for (int mt = 0; mt < 2; mt++)
        #pragma unroll
        for (int nt = 0; nt < 8; nt++)
            #pragma unroll
            for (int q = 0; q < 4; q++) acc[mt][nt][q] = 0.f;

    // ldmatrix lane address offsets (within tile, excluding kstep/term bases)
    const u32 aoff = (u32)((w * 32 + (lane & 15)) * PITCH + ((lane >> 4) & 1) * 16);
    const u32 boff = (u32)((((lane >> 4) & 1) * 8 + (lane & 7)) * PITCH
                           + ((lane >> 3) & 1) * 16);

    // 3 terms: Ahi*Bhi, Ahi*Blo, Alo*Bhi
    #pragma unroll
    for (int term = 0; term < 3; term++) {
        const u32 abase = sb + ((term == 2) ? OFF_ALO : OFF_AHI) + aoff;
        const u32 bbase = sb + ((term == 1) ? OFF_BLO : OFF_BHI) + boff;
        #pragma unroll
        for (int ks = 0; ks < 4; ks++) {
            u32 a[2][4];
            LDSM4(a[0][0], a[0][1], a[0][2], a[0][3], abase + ks * 32);
            LDSM4(a[1][0], a[1][1], a[1][2], a[1][3], abase + ks * 32 + 16 * PITCH);
            u32 bf[8][2];
            #pragma unroll
            for (int q = 0; q < 4; q++) {
                LDSM4(bf[2 * q][0], bf[2 * q][1], bf[2 * q + 1][0], bf[2 * q + 1][1],
                      bbase + ks * 32 + q * 16 * PITCH);
            }
            #pragma unroll
            for (int mt = 0; mt < 2; mt++)
                #pragma unroll
                for (int nt = 0; nt < 8; nt++)
                    mma16816(acc[mt][nt], a[mt], bf[nt][0], bf[nt][1]);
        }
    }

    // Epilogue: tanh + v-weighted o-reduction; lanes share j across c=lane&3
    {
        const int g = lane >> 2, c = lane & 3;
        float2 vv2[8], bv2[8];
        #pragma unroll
        for (int nt = 0; nt < 8; nt++) {
            vv2[nt] = *(const float2*)&vv[nt * 8 + 2 * c];
            bv2[nt] = *(const float2*)&bv[nt * 8 + 2 * c];
        }
        #pragma unroll
        for (int mt = 0; mt < 2; mt++) {
            #pragma unroll
            for (int rh = 0; rh < 2; rh++) {
                float s = 0.f;
                #pragma unroll
                for (int nt = 0; nt < 8; nt++) {
                    s += vv2[nt].x * fast_tanh(acc[mt][nt][2 * rh]     + bv2[nt].x);
                    s += vv2[nt].y * fast_tanh(acc[mt][nt][2 * rh + 1] + bv2[nt].y);
                }
                s += __shfl_xor_sync(~0u, s, 1);
                s += __shfl_xor_sync(~0u, s, 2);
                if (c == 0) {
                    int jloc = w * 32 + mt * 16 + rh * 8 + g;
                    int jg = (i + jloc) & (NN - 1);
                    g_L[((size_t)b * NN + i) * NN + jg] = s;
                    g_L[((size_t)b * NN + jg) * NN + i] = s;   // symmetric mirror
                }
            }
        }
    }

    // Tail k=256 (single writer i<256), exact fp32 scalar
    if (i < 256) {
        float* red = (float*)(smem + OFF_RED);
        if (tid < 64) {
            float q2 = bv[tid];
            const float* xj = xb + (size_t)(i + 256) * DD;
            #pragma unroll 8
            for (int d = 0; d < 64; d++)
                q2 = fmaf(xi[d] * attw[d * 64 + tid], xj[d], q2);
            red[tid] = vv[tid] * fast_tanh(q2);
        }
        __syncthreads();
        if (tid == 0) {
            float s = 0.f;
            for (int o = 0; o < 64; o++) s += red[o];
            int jg = i + 256;
            g_L[((size_t)b * NN + i) * NN + jg] = s;
            g_L[((size_t)b * NN + jg) * NN + i] = s;
        }
    }
}

// ---------------------------------------------------------------------------
// Kernel 2 (tiled, 512 threads): unchanged proven version.
// ---------------------------------------------------------------------------
#define ITILE 32
__global__ __launch_bounds__(512, 1) void k2_head(
    const float* __restrict__ x,
    const float* __restrict__ pwa_w, const float* __restrict__ pwa_b,
    const float* __restrict__ pwo_w, const float* __restrict__ pwo_b,
    const float* __restrict__ gamma, const float* __restrict__ beta,
    const float* __restrict__ poolw, const float* __restrict__ poolb)
{
    extern __shared__ float s2[];
    float* att = s2;                       // [32][512] (reused as hsm later)
    float* xs  = s2 + ITILE * NN;          // [512][64]
    float* agg = xs + NN * DD;             // [32][64]
    float* inv = agg + ITILE * DD;         // [32]
    float* hsm = att;

    const int itile = blockIdx.x, b = blockIdx.y;
    const int tid = threadIdx.x;
    const int wid = tid >> 5, lane = tid & 31;

    {
        const float4* Ls = (const float4*)(g_L + ((size_t)b * NN + itile * ITILE) * NN);
        float4* Ld = (float4*)att;
        for (int idx = tid; idx < ITILE * NN / 4; idx += 512) Ld[idx] = Ls[idx];
        const float4* Xs = (const float4*)(x + (size_t)b * NN * DD);
        float4* Xd = (float4*)xs;
        for (int idx = tid; idx < NN * DD / 4; idx += 512) Xd[idx] = Xs[idx];
    }
    __syncthreads();

    #pragma unroll
    for (int rr = 0; rr < 2; rr++) {
        int r = wid + rr * 16;
        float* row = att + r * NN;
        float m = -1e30f;
        #pragma unroll 4
        for (int j = lane; j < NN; j += 32) m = fmaxf(m, row[j]);
        #pragma unroll
        for (int off = 16; off; off >>= 1) m = fmaxf(m, __shfl_xor_sync(~0u, m, off));
        float ssum = 0.f;
        #pragma unroll 4
        for (int j = lane; j < NN; j += 32) {
            float e = __expf(row[j] - m);
            row[j] = e;
            ssum += e;
        }
        #pragma unroll
        for (int off = 16; off; off >>= 1) ssum += __shfl_xor_sync(~0u, ssum, off);
        if (lane == 0) inv[r] = 1.0f / ssum;
    }
    __syncthreads();

    const int d = tid & 63, ig = tid >> 6;
    float acc[4] = {0, 0, 0, 0};
    for (int j = 0; j < NN; j += 4) {
        float x0 = xs[(j + 0) * DD + d];
        float x1 = xs[(j + 1) * DD + d];
        float x2 = xs[(j + 2) * DD + d];
        float x3 = xs[(j + 3) * DD + d];
        #pragma unroll
        for (int s = 0; s < 4; s++) {
            float4 a = *(const float4*)&att[(ig * 4 + s) * NN + j];
            acc[s] = fmaf(a.x, x0, acc[s]);
            acc[s] = fmaf(a.y, x1, acc[s]);
            acc[s] = fmaf(a.z, x2, acc[s]);
            acc[s] = fmaf(a.w, x3, acc[s]);
        }
    }
    __syncthreads();
    #pragma unroll
    for (int s = 0; s < 4; s++)
        agg[(ig * 4 + s) * DD + d] = acc[s] * inv[ig * 4 + s];
    __syncthreads();

    {
        const int o = d;
        float hv[4];
        float pb = pwa_b[o] + pwo_b[o];
        #pragma unroll
        for (int s = 0; s < 4; s++) hv[s] = pb;
        #pragma unroll 8
        for (int dd = 0; dd < 64; dd++) {
            float wa = __ldg(&pwa_w[dd * 64 + o]);
            float wo = __ldg(&pwo_w[dd * 64 + o]);
            #pragma unroll
            for (int s = 0; s < 4; s++) {
                int ii = ig * 4 + s;
                hv[s] = fmaf(agg[ii * DD + dd], wa, hv[s]);
                hv[s] = fmaf(xs[(itile * ITILE + ii) * DD + dd], wo, hv[s]);
            }
        }
        const float BNS = 0.99999500003749969f;
        float gam = gamma[o] * BNS, bet = beta[o];
        const float SC = 1.0507009873554804934193349852946f;
        const float AL = 1.6732632423543772848170429916717f;
        #pragma unroll
        for (int s = 0; s < 4; s++) {
            float h = fmaf(hv[s], gam, bet);
            h = h > 0.f ? SC * h : SC * AL * expm1f(h);
            hsm[(ig * 4 + s) * DD + o] = h;
        }
    }
    __syncthreads();

    if (tid < ITILE) {
        float z = poolb[0];
        #pragma unroll 8
        for (int oo = 0; oo < 64; oo++) z = fmaf(hsm[tid * 64 + oo], poolw[oo], z);
        g_s[(size_t)b * NN + itile * ITILE + tid] = 1.0f / (1.0f + expf(-z));
    }
    {
        float4* gh = (float4*)(g_h + ((size_t)b * NN + itile * ITILE) * DD);
        const float4* hs = (const float4*)hsm;
        for (int idx = tid; idx < ITILE * DD / 4; idx += 512) gh[idx] = hs[idx];
    }
}

// ---------------------------------------------------------------------------
// Kernel 3: per batch, descending top-256 (stable), gather h*score
// ---------------------------------------------------------------------------
__global__ __launch_bounds__(512) void k3_topk(float* __restrict__ out)
{
    __shared__ ull keys[NN];
    const int b = blockIdx.x, tid = threadIdx.x;
    {
        float sc = g_s[(size_t)b * NN + tid];
        keys[tid] = ((ull)__float_as_uint(sc) << 32) | (ull)(unsigned)(511 - tid);
    }
    __syncthreads();
    for (int k = 2; k <= NN; k <<= 1) {
        for (int j = k >> 1; j > 0; j >>= 1) {
            int ixj = tid ^ j;
            if (ixj > tid) {
                ull a = keys[tid], c = keys[ixj];
                bool asc = (tid & k) == 0;
                if ((a > c) == asc) { keys[tid] = c; keys[ixj] = a; }
            }
            __syncthreads();
        }
    }
    const int r = tid >> 1, ho = (tid & 1) * 32;
    ull key = keys[(NN - 1) - r];
    float sc = __uint_as_float((unsigned)(key >> 32));
    int idx = 511 - (int)(key & 0xffffffffu);
    const float* hr = &g_h[((size_t)b * NN + idx) * DD];
    float* orow = &out[((size_t)b * KSEL + r) * DD];
    #pragma unroll
    for (int c = 0; c < 32; c++)
        orow[ho + c] = hr[ho + c] * sc;
}

// ---------------------------------------------------------------------------
extern "C" void kernel_launch(void* const* d_in, const int* in_sizes, int n_in,
                              void* d_out, int out_size)
{
    (void)in_sizes; (void)n_in; (void)out_size;
    const float* x      = (const float*)d_in[0];
    const float* attw   = (const float*)d_in[1];
    const float* attb   = (const float*)d_in[2];
    const float* attv   = (const float*)d_in[3];
    const float* pwa_w  = (const float*)d_in[4];
    const float* pwa_b  = (const float*)d_in[5];
    const float* pwo_w  = (const float*)d_in[6];
    const float* pwo_b  = (const float*)d_in[7];
    const float* gamma  = (const float*)d_in[8];
    const float* beta   = (const float*)d_in[9];
    const float* poolw  = (const float*)d_in[10];
    const float* poolb  = (const float*)d_in[11];

    cudaFuncSetAttribute(k1_logits, cudaFuncAttributeMaxDynamicSharedMemorySize, SMEM1);
    const int SMEM2 = (ITILE * NN + NN * DD + ITILE * DD + ITILE) * (int)sizeof(float);
    cudaFuncSetAttribute(k2_head, cudaFuncAttributeMaxDynamicSharedMemorySize, SMEM2);

    dim3 g1(NN, BB);
    k1_logits<<<g1, 256, SMEM1>>>(x, attw, attb, attv);
    dim3 g2(NN / ITILE, BB);
    k2_head<<<g2, 512, SMEM2>>>(x, pwa_w, pwa_b, pwo_w, pwo_b, gamma, beta, poolw, poolb);
    k3_topk<<<BB, NN>>>((float*)d_out);
}

// round 7
// speedup vs baseline: 1.5871x; 1.0369x over previous
#include <cuda_runtime.h>
#include <cuda_fp16.h>
#include <cstdint>
#include <math.h>

typedef unsigned long long ull;
typedef unsigned int u32;

#define NN 512
#define DD 64
#define BB 8
#define KSEL 256
#define G 4                   // i-values per CTA in k1

// Scratch (no allocation allowed)
__device__ float g_L[(size_t)BB * NN * NN];   // logits  8 MB
__device__ float g_h[(size_t)BB * NN * DD];   // h after selu
__device__ float g_s[(size_t)BB * NN];        // sigmoid scores
__device__ __half2 g_xhi[(size_t)BB * NN * 32];  // fp16 hi of x
__device__ __half2 g_xlo[(size_t)BB * NN * 32];  // fp16 lo residual

// Fast tanh: ex2.approx + rcp.approx + 1 Newton step. abs err ~1e-7.
__device__ __forceinline__ float fast_tanh(float x) {
    float ax = fabsf(x), t, r;
    asm("ex2.approx.f32 %0, %1;" : "=f"(t) : "f"(ax * -2.8853900817779268f));
    float u = 1.0f + t;
    asm("rcp.approx.f32 %0, %1;" : "=f"(r) : "f"(u));
    r = r * fmaf(-u, r, 2.0f);
    return copysignf((1.0f - t) * r, x);
}

__device__ __forceinline__ u32 smem_u32(const void* p) {
    u32 a;
    asm("{ .reg .u64 t; cvta.to.shared.u64 t, %1; cvt.u32.u64 %0, t; }" : "=r"(a) : "l"(p));
    return a;
}

#define LDSM4(r0, r1, r2, r3, a) \
    asm volatile("ldmatrix.sync.aligned.m8n8.x4.shared.b16 {%0,%1,%2,%3}, [%4];" \
        : "=r"(r0), "=r"(r1), "=r"(r2), "=r"(r3) : "r"(a))

__device__ __forceinline__ void mma16816(float* c, const u32* a, u32 b0, u32 b1) {
    asm volatile(
        "mma.sync.aligned.m16n8k16.row.col.f32.f16.f16.f32 "
        "{%0,%1,%2,%3}, {%4,%5,%6,%7}, {%8,%9}, {%0,%1,%2,%3};"
        : "+f"(c[0]), "+f"(c[1]), "+f"(c[2]), "+f"(c[3])
        : "r"(a[0]), "r"(a[1]), "r"(a[2]), "r"(a[3]), "r"(b0), "r"(b1));
}

// ---------------- Kernel 0: convert x to fp16 hi/lo (once) ----------------
__global__ __launch_bounds__(256) void k0_cvt(const float* __restrict__ x)
{
    int t = blockIdx.x * 256 + threadIdx.x;   // over 131072 float2
    float2 v = ((const float2*)x)[t];
    __half h0 = __float2half_rn(v.x), h1 = __float2half_rn(v.y);
    __half l0 = __float2half_rn(v.x - __half2float(h0));
    __half l1 = __float2half_rn(v.y - __half2float(h1));
    g_xhi[t] = __halves2half2(h0, h1);
    g_xlo[t] = __halves2half2(l0, l1);
}

// ---------------- Kernel 1: logits via HMMA fp16 hi/lo, G=4 i per CTA ------
#define PITCH 144            // bytes per fp16 row of 64 (128B data + 16B pad)
#define RWIN  260            // window rows: 256 + G
#define OFF_XI  0
#define OFF_VV  256
#define OFF_BV  512
#define OFF_RED 768
#define OFF_AHI 1024
#define OFF_ALO (OFF_AHI + RWIN * PITCH)
#define OFF_BHI (OFF_ALO + RWIN * PITCH)
#define OFF_BLO (OFF_BHI + 64 * PITCH)
#define SMEM1   (OFF_BLO + 64 * PITCH)      // 94336 bytes

__global__ __launch_bounds__(256, 2) void k1_logits(
    const float* __restrict__ x, const float* __restrict__ attw,
    const float* __restrict__ attb, const float* __restrict__ attv)
{
    extern __shared__ char smem[];
    const u32 sb = smem_u32(smem);
    const int tid = threadIdx.x, w = tid >> 5, lane = tid & 31;
    const int i0 = blockIdx.x * G, b = blockIdx.y;

    float* xi = (float*)(smem + OFF_XI);
    float* vv = (float*)(smem + OFF_VV);
    float* bv = (float*)(smem + OFF_BV);
    float* red = (float*)(smem + OFF_RED);

    if (tid < 64) { vv[tid] = attv[tid]; bv[tid] = attb[tid]; }

    // A fill: copy precomputed fp16 hi/lo rows (i0..i0+259 mod 512)
    {
        const float4* xh4 = (const float4*)g_xhi;
        const float4* xl4 = (const float4*)g_xlo;
        for (int idx = tid; idx < RWIN * 8; idx += 256) {
            int r = idx >> 3, c = idx & 7;
            int grow = (i0 + r) & (NN - 1);
            size_t src = (size_t)(b * NN + grow) * 8 + c;
            u32 dst = (u32)(r * PITCH + c * 16);
            *(float4*)(smem + OFF_AHI + dst) = xh4[src];
            *(float4*)(smem + OFF_ALO + dst) = xl4[src];
        }
    }

    // ldmatrix lane address offsets
    const u32 aoff = (u32)((w * 32 + (lane & 15)) * PITCH + ((lane >> 4) & 1) * 16);
    const u32 boff = (u32)((((lane >> 4) & 1) * 8 + (lane & 7)) * PITCH
                           + ((lane >> 3) & 1) * 16);

    const float* xb = x + (size_t)b * NN * DD;

    for (int g = 0; g < G; g++) {
        const int i = i0 + g;
        __syncthreads();   // prev-g B reads + red/xi uses done
        if (tid < 64) xi[tid] = xb[(size_t)i * DD + tid];
        __syncthreads();   // xi visible

        // B fill: B[o][d] = x_i[d] * W[d][o], fp16 hi/lo
        for (int idx = tid; idx < 64 * 64; idx += 256) {
            int d = idx >> 6, o = idx & 63;
            float wv2 = xi[d] * attw[idx];
            __half h = __float2half_rn(wv2);
            __half l = __float2half_rn(wv2 - __half2float(h));
            *(__half*)(smem + OFF_BHI + o * PITCH + 2 * d) = h;
            *(__half*)(smem + OFF_BLO + o * PITCH + 2 * d) = l;
        }
        __syncthreads();   // A (first g) + B visible

        // Per-warp output block: 32 j (2 m16 tiles) x 64 o (8 n8 tiles)
        float acc[2][8][4];
        #pragma unroll
        for (int mt = 0; mt < 2; mt++)
            #pragma unroll
            for (int nt = 0; nt < 8; nt++)
                #pragma unroll
                for (int q = 0; q < 4; q++) acc[mt][nt][q] = 0.f;

        // 3 terms: Ahi*Bhi, Ahi*Blo, Alo*Bhi
        #pragma unroll
        for (int term = 0; term < 3; term++) {
            const u32 abase = sb + ((term == 2) ? OFF_ALO : OFF_AHI) + aoff
                            + (u32)(g * PITCH);
            const u32 bbase = sb + ((term == 1) ? OFF_BLO : OFF_BHI) + boff;
            #pragma unroll
            for (int ks = 0; ks < 4; ks++) {
                u32 a[2][4];
                LDSM4(a[0][0], a[0][1], a[0][2], a[0][3], abase + ks * 32);
                LDSM4(a[1][0], a[1][1], a[1][2], a[1][3], abase + ks * 32 + 16 * PITCH);
                u32 bf[8][2];
                #pragma unroll
                for (int q = 0; q < 4; q++) {
                    LDSM4(bf[2 * q][0], bf[2 * q][1], bf[2 * q + 1][0], bf[2 * q + 1][1],
                          bbase + ks * 32 + q * 16 * PITCH);
                }
                #pragma unroll
                for (int mt = 0; mt < 2; mt++)
                    #pragma unroll
                    for (int nt = 0; nt < 8; nt++)
                        mma16816(acc[mt][nt], a[mt], bf[nt][0], bf[nt][1]);
            }
        }

        // Epilogue: tanh + v-weighted o-reduction; lanes share j across c=lane&3
        {
            const int gq = lane >> 2, c = lane & 3;
            float2 vv2[8], bv2[8];
            #pragma unroll
            for (int nt = 0; nt < 8; nt++) {
                vv2[nt] = *(const float2*)&vv[nt * 8 + 2 * c];
                bv2[nt] = *(const float2*)&bv[nt * 8 + 2 * c];
            }
            #pragma unroll
            for (int mt = 0; mt < 2; mt++) {
                #pragma unroll
                for (int rh = 0; rh < 2; rh++) {
                    float s = 0.f;
                    #pragma unroll
                    for (int nt = 0; nt < 8; nt++) {
                        s += vv2[nt].x * fast_tanh(acc[mt][nt][2 * rh]     + bv2[nt].x);
                        s += vv2[nt].y * fast_tanh(acc[mt][nt][2 * rh + 1] + bv2[nt].y);
                    }
                    s += __shfl_xor_sync(~0u, s, 1);
                    s += __shfl_xor_sync(~0u, s, 2);
                    if (c == 0) {
                        int jloc = w * 32 + mt * 16 + rh * 8 + gq;
                        int jg = (i + jloc) & (NN - 1);
                        g_L[((size_t)b * NN + i) * NN + jg] = s;
                        g_L[((size_t)b * NN + jg) * NN + i] = s;  // mirror
                    }
                }
            }
        }

        // Tail k=256 (single writer i<256), exact fp32 scalar
        if (i0 < 256) {
            if (tid < 64) {
                float q2 = bv[tid];
                const float* xj = xb + (size_t)(i + 256) * DD;
                #pragma unroll 8
                for (int d = 0; d < 64; d++)
                    q2 = fmaf(xi[d] * attw[d * 64 + tid], xj[d], q2);
                red[tid] = vv[tid] * fast_tanh(q2);
            }
            __syncthreads();
            if (tid == 0) {
                float s = 0.f;
                for (int o = 0; o < 64; o++) s += red[o];
                int jg = i + 256;
                g_L[((size_t)b * NN + i) * NN + jg] = s;
                g_L[((size_t)b * NN + jg) * NN + i] = s;
            }
        }
    }
}

// ---------------------------------------------------------------------------
// Kernel 2 (tiled, 512 threads): unchanged proven version.
// ---------------------------------------------------------------------------
#define ITILE 32
__global__ __launch_bounds__(512, 1) void k2_head(
    const float* __restrict__ x,
    const float* __restrict__ pwa_w, const float* __restrict__ pwa_b,
    const float* __restrict__ pwo_w, const float* __restrict__ pwo_b,
    const float* __restrict__ gamma, const float* __restrict__ beta,
    const float* __restrict__ poolw, const float* __restrict__ poolb)
{
    extern __shared__ float s2[];
    float* att = s2;                       // [32][512] (reused as hsm later)
    float* xs  = s2 + ITILE * NN;          // [512][64]
    float* agg = xs + NN * DD;             // [32][64]
    float* inv = agg + ITILE * DD;         // [32]
    float* hsm = att;

    const int itile = blockIdx.x, b = blockIdx.y;
    const int tid = threadIdx.x;
    const int wid = tid >> 5, lane = tid & 31;

    {
        const float4* Ls = (const float4*)(g_L + ((size_t)b * NN + itile * ITILE) * NN);
        float4* Ld = (float4*)att;
        for (int idx = tid; idx < ITILE * NN / 4; idx += 512) Ld[idx] = Ls[idx];
        const float4* Xs = (const float4*)(x + (size_t)b * NN * DD);
        float4* Xd = (float4*)xs;
        for (int idx = tid; idx < NN * DD / 4; idx += 512) Xd[idx] = Xs[idx];
    }
    __syncthreads();

    #pragma unroll
    for (int rr = 0; rr < 2; rr++) {
        int r = wid + rr * 16;
        float* row = att + r * NN;
        float m = -1e30f;
        #pragma unroll 4
        for (int j = lane; j < NN; j += 32) m = fmaxf(m, row[j]);
        #pragma unroll
        for (int off = 16; off; off >>= 1) m = fmaxf(m, __shfl_xor_sync(~0u, m, off));
        float ssum = 0.f;
        #pragma unroll 4
        for (int j = lane; j < NN; j += 32) {
            float e = __expf(row[j] - m);
            row[j] = e;
            ssum += e;
        }
        #pragma unroll
        for (int off = 16; off; off >>= 1) ssum += __shfl_xor_sync(~0u, ssum, off);
        if (lane == 0) inv[r] = 1.0f / ssum;
    }
    __syncthreads();

    const int d = tid & 63, ig = tid >> 6;
    float acc[4] = {0, 0, 0, 0};
    for (int j = 0; j < NN; j += 4) {
        float x0 = xs[(j + 0) * DD + d];
        float x1 = xs[(j + 1) * DD + d];
        float x2 = xs[(j + 2) * DD + d];
        float x3 = xs[(j + 3) * DD + d];
        #pragma unroll
        for (int s = 0; s < 4; s++) {
            float4 a = *(const float4*)&att[(ig * 4 + s) * NN + j];
            acc[s] = fmaf(a.x, x0, acc[s]);
            acc[s] = fmaf(a.y, x1, acc[s]);
            acc[s] = fmaf(a.z, x2, acc[s]);
            acc[s] = fmaf(a.w, x3, acc[s]);
        }
    }
    __syncthreads();
    #pragma unroll
    for (int s = 0; s < 4; s++)
        agg[(ig * 4 + s) * DD + d] = acc[s] * inv[ig * 4 + s];
    __syncthreads();

    {
        const int o = d;
        float hv[4];
        float pb = pwa_b[o] + pwo_b[o];
        #pragma unroll
        for (int s = 0; s < 4; s++) hv[s] = pb;
        #pragma unroll 8
        for (int dd = 0; dd < 64; dd++) {
            float wa = __ldg(&pwa_w[dd * 64 + o]);
            float wo = __ldg(&pwo_w[dd * 64 + o]);
            #pragma unroll
            for (int s = 0; s < 4; s++) {
                int ii = ig * 4 + s;
                hv[s] = fmaf(agg[ii * DD + dd], wa, hv[s]);
                hv[s] = fmaf(xs[(itile * ITILE + ii) * DD + dd], wo, hv[s]);
            }
        }
        const float BNS = 0.99999500003749969f;
        float gam = gamma[o] * BNS, bet = beta[o];
        const float SC = 1.0507009873554804934193349852946f;
        const float AL = 1.6732632423543772848170429916717f;
        #pragma unroll
        for (int s = 0; s < 4; s++) {
            float h = fmaf(hv[s], gam, bet);
            h = h > 0.f ? SC * h : SC * AL * expm1f(h);
            hsm[(ig * 4 + s) * DD + o] = h;
        }
    }
    __syncthreads();

    if (tid < ITILE) {
        float z = poolb[0];
        #pragma unroll 8
        for (int oo = 0; oo < 64; oo++) z = fmaf(hsm[tid * 64 + oo], poolw[oo], z);
        g_s[(size_t)b * NN + itile * ITILE + tid] = 1.0f / (1.0f + expf(-z));
    }
    {
        float4* gh = (float4*)(g_h + ((size_t)b * NN + itile * ITILE) * DD);
        const float4* hs = (const float4*)hsm;
        for (int idx = tid; idx < ITILE * DD / 4; idx += 512) gh[idx] = hs[idx];
    }
}

// ---------------------------------------------------------------------------
// Kernel 3: per batch, descending top-256 (stable), gather h*score
// ---------------------------------------------------------------------------
__global__ __launch_bounds__(512) void k3_topk(float* __restrict__ out)
{
    __shared__ ull keys[NN];
    const int b = blockIdx.x, tid = threadIdx.x;
    {
        float sc = g_s[(size_t)b * NN + tid];
        keys[tid] = ((ull)__float_as_uint(sc) << 32) | (ull)(unsigned)(511 - tid);
    }
    __syncthreads();
    for (int k = 2; k <= NN; k <<= 1) {
        for (int j = k >> 1; j > 0; j >>= 1) {
            int ixj = tid ^ j;
            if (ixj > tid) {
                ull a = keys[tid], c = keys[ixj];
                bool asc = (tid & k) == 0;
                if ((a > c) == asc) { keys[tid] = c; keys[ixj] = a; }
            }
            __syncthreads();
        }
    }
    const int r = tid >> 1, ho = (tid & 1) * 32;
    ull key = keys[(NN - 1) - r];
    float sc = __uint_as_float((unsigned)(key >> 32));
    int idx = 511 - (int)(key & 0xffffffffu);
    const float* hr = &g_h[((size_t)b * NN + idx) * DD];
    float* orow = &out[((size_t)b * KSEL + r) * DD];
    #pragma unroll
    for (int c = 0; c < 32; c++)
        orow[ho + c] = hr[ho + c] * sc;
}

// ---------------------------------------------------------------------------
extern "C" void kernel_launch(void* const* d_in, const int* in_sizes, int n_in,
                              void* d_out, int out_size)
{
    (void)in_sizes; (void)n_in; (void)out_size;
    const float* x      = (const float*)d_in[0];
    const float* attw   = (const float*)d_in[1];
    const float* attb   = (const float*)d_in[2];
    const float* attv   = (const float*)d_in[3];
    const float* pwa_w  = (const float*)d_in[4];
    const float* pwa_b  = (const float*)d_in[5];
    const float* pwo_w  = (const float*)d_in[6];
    const float* pwo_b  = (const float*)d_in[7];
    const float* gamma  = (const float*)d_in[8];
    const float* beta   = (const float*)d_in[9];
    const float* poolw  = (const float*)d_in[10];
    const float* poolb  = (const float*)d_in[11];

    cudaFuncSetAttribute(k1_logits, cudaFuncAttributeMaxDynamicSharedMemorySize, SMEM1);
    const int SMEM2 = (ITILE * NN + NN * DD + ITILE * DD + ITILE) * (int)sizeof(float);
    cudaFuncSetAttribute(k2_head, cudaFuncAttributeMaxDynamicSharedMemorySize, SMEM2);

    k0_cvt<<<BB * NN * 32 / 256, 256>>>(x);
    dim3 g1(NN / G, BB);
    k1_logits<<<g1, 256, SMEM1>>>(x, attw, attb, attv);
    dim3 g2(NN / ITILE, BB);
    k2_head<<<g2, 512, SMEM2>>>(x, pwa_w, pwa_b, pwo_w, pwo_b, gamma, beta, poolw, poolb);
    k3_topk<<<BB, NN>>>((float*)d_out);
}

// round 8
// speedup vs baseline: 1.6857x; 1.0621x over previous
#include <cuda_runtime.h>
#include <cuda_fp16.h>
#include <cstdint>
#include <math.h>

typedef unsigned long long ull;
typedef unsigned int u32;

#define NN 512
#define DD 64
#define BB 8
#define KSEL 256
#define G 4                   // i-values per CTA in k1

// Scratch (no allocation allowed)
__device__ float g_L[(size_t)BB * NN * NN];   // logits  8 MB
__device__ float g_h[(size_t)BB * NN * DD];   // h after selu
__device__ float g_s[(size_t)BB * NN];        // sigmoid scores
__device__ __half2 g_xhi[(size_t)BB * NN * 32];  // fp16 hi of x
__device__ __half2 g_xlo[(size_t)BB * NN * 32];  // fp16 lo residual

// Fast tanh: ex2.approx + rcp.approx + 1 Newton step. abs err ~1e-7.
__device__ __forceinline__ float fast_tanh(float x) {
    float ax = fabsf(x), t, r;
    asm("ex2.approx.f32 %0, %1;" : "=f"(t) : "f"(ax * -2.8853900817779268f));
    float u = 1.0f + t;
    asm("rcp.approx.f32 %0, %1;" : "=f"(r) : "f"(u));
    r = r * fmaf(-u, r, 2.0f);
    return copysignf((1.0f - t) * r, x);
}

__device__ __forceinline__ u32 smem_u32(const void* p) {
    u32 a;
    asm("{ .reg .u64 t; cvta.to.shared.u64 t, %1; cvt.u32.u64 %0, t; }" : "=r"(a) : "l"(p));
    return a;
}

#define LDSM4(r0, r1, r2, r3, a) \
    asm volatile("ldmatrix.sync.aligned.m8n8.x4.shared.b16 {%0,%1,%2,%3}, [%4];" \
        : "=r"(r0), "=r"(r1), "=r"(r2), "=r"(r3) : "r"(a))

__device__ __forceinline__ void mma16816(float* c, const u32* a, u32 b0, u32 b1) {
    asm volatile(
        "mma.sync.aligned.m16n8k16.row.col.f32.f16.f16.f32 "
        "{%0,%1,%2,%3}, {%4,%5,%6,%7}, {%8,%9}, {%0,%1,%2,%3};"
        : "+f"(c[0]), "+f"(c[1]), "+f"(c[2]), "+f"(c[3])
        : "r"(a[0]), "r"(a[1]), "r"(a[2]), "r"(a[3]), "r"(b0), "r"(b1));
}

// ---------------- Kernel 0: convert x to fp16 hi/lo (once) ----------------
__global__ __launch_bounds__(256) void k0_cvt(const float* __restrict__ x)
{
    int t = blockIdx.x * 256 + threadIdx.x;   // over 131072 float2
    float2 v = ((const float2*)x)[t];
    __half h0 = __float2half_rn(v.x), h1 = __float2half_rn(v.y);
    __half l0 = __float2half_rn(v.x - __half2float(h0));
    __half l1 = __float2half_rn(v.y - __half2float(h1));
    g_xhi[t] = __halves2half2(h0, h1);
    g_xlo[t] = __halves2half2(l0, l1);
}

// ---------------- Kernel 1: logits via HMMA fp16 hi/lo, G=4 i per CTA ------
#define PITCH 144            // bytes per fp16 row of 64 (128B data + 16B pad)
#define RWIN  260            // window rows: 256 + G
#define OFF_XI  0
#define OFF_VV  256
#define OFF_BV  512
#define OFF_RED 768
#define OFF_AHI 1024
#define OFF_ALO (OFF_AHI + RWIN * PITCH)
#define OFF_BHI (OFF_ALO + RWIN * PITCH)
#define OFF_BLO (OFF_BHI + 64 * PITCH)
#define SMEM1   (OFF_BLO + 64 * PITCH)      // 94336 bytes

__global__ __launch_bounds__(256, 2) void k1_logits(
    const float* __restrict__ x, const float* __restrict__ attw,
    const float* __restrict__ attb, const float* __restrict__ attv)
{
    extern __shared__ char smem[];
    const u32 sb = smem_u32(smem);
    const int tid = threadIdx.x, w = tid >> 5, lane = tid & 31;
    const int i0 = blockIdx.x * G, b = blockIdx.y;

    float* xi = (float*)(smem + OFF_XI);
    float* vv = (float*)(smem + OFF_VV);
    float* bv = (float*)(smem + OFF_BV);
    float* red = (float*)(smem + OFF_RED);

    if (tid < 64) { vv[tid] = attv[tid]; bv[tid] = attb[tid]; }

    // A fill: copy precomputed fp16 hi/lo rows (i0..i0+259 mod 512)
    {
        const float4* xh4 = (const float4*)g_xhi;
        const float4* xl4 = (const float4*)g_xlo;
        for (int idx = tid; idx < RWIN * 8; idx += 256) {
            int r = idx >> 3, c = idx & 7;
            int grow = (i0 + r) & (NN - 1);
            size_t src = (size_t)(b * NN + grow) * 8 + c;
            u32 dst = (u32)(r * PITCH + c * 16);
            *(float4*)(smem + OFF_AHI + dst) = xh4[src];
            *(float4*)(smem + OFF_ALO + dst) = xl4[src];
        }
    }

    // ldmatrix lane address offsets
    const u32 aoff = (u32)((w * 32 + (lane & 15)) * PITCH + ((lane >> 4) & 1) * 16);
    const u32 boff = (u32)((((lane >> 4) & 1) * 8 + (lane & 7)) * PITCH
                           + ((lane >> 3) & 1) * 16);

    const float* xb = x + (size_t)b * NN * DD;

    for (int g = 0; g < G; g++) {
        const int i = i0 + g;
        __syncthreads();   // prev-g B reads + red/xi uses done
        if (tid < 64) xi[tid] = xb[(size_t)i * DD + tid];
        __syncthreads();   // xi visible

        // B fill: B[o][d] = x_i[d] * W[d][o], fp16 hi/lo
        for (int idx = tid; idx < 64 * 64; idx += 256) {
            int d = idx >> 6, o = idx & 63;
            float wv2 = xi[d] * attw[idx];
            __half h = __float2half_rn(wv2);
            __half l = __float2half_rn(wv2 - __half2float(h));
            *(__half*)(smem + OFF_BHI + o * PITCH + 2 * d) = h;
            *(__half*)(smem + OFF_BLO + o * PITCH + 2 * d) = l;
        }
        __syncthreads();   // A (first g) + B visible

        // Per-warp output block: 32 j (2 m16 tiles) x 64 o (8 n8 tiles)
        float acc[2][8][4];
        #pragma unroll
        for (int mt = 0; mt < 2; mt++)
            #pragma unroll
            for (int nt = 0; nt < 8; nt++)
                #pragma unroll
                for (int q = 0; q < 4; q++) acc[mt][nt][q] = 0.f;

        // 3 terms: Ahi*Bhi, Ahi*Blo, Alo*Bhi
        #pragma unroll
        for (int term = 0; term < 3; term++) {
            const u32 abase = sb + ((term == 2) ? OFF_ALO : OFF_AHI) + aoff
                            + (u32)(g * PITCH);
            const u32 bbase = sb + ((term == 1) ? OFF_BLO : OFF_BHI) + boff;
            #pragma unroll
            for (int ks = 0; ks < 4; ks++) {
                u32 a[2][4];
                LDSM4(a[0][0], a[0][1], a[0][2], a[0][3], abase + ks * 32);
                LDSM4(a[1][0], a[1][1], a[1][2], a[1][3], abase + ks * 32 + 16 * PITCH);
                u32 bf[8][2];
                #pragma unroll
                for (int q = 0; q < 4; q++) {
                    LDSM4(bf[2 * q][0], bf[2 * q][1], bf[2 * q + 1][0], bf[2 * q + 1][1],
                          bbase + ks * 32 + q * 16 * PITCH);
                }
                #pragma unroll
                for (int mt = 0; mt < 2; mt++)
                    #pragma unroll
                    for (int nt = 0; nt < 8; nt++)
                        mma16816(acc[mt][nt], a[mt], bf[nt][0], bf[nt][1]);
            }
        }

        // Epilogue: tanh + v-weighted o-reduction; lanes share j across c=lane&3
        {
            const int gq = lane >> 2, c = lane & 3;
            float2 vv2[8], bv2[8];
            #pragma unroll
            for (int nt = 0; nt < 8; nt++) {
                vv2[nt] = *(const float2*)&vv[nt * 8 + 2 * c];
                bv2[nt] = *(const float2*)&bv[nt * 8 + 2 * c];
            }
            #pragma unroll
            for (int mt = 0; mt < 2; mt++) {
                #pragma unroll
                for (int rh = 0; rh < 2; rh++) {
                    float s = 0.f;
                    #pragma unroll
                    for (int nt = 0; nt < 8; nt++) {
                        s += vv2[nt].x * fast_tanh(acc[mt][nt][2 * rh]     + bv2[nt].x);
                        s += vv2[nt].y * fast_tanh(acc[mt][nt][2 * rh + 1] + bv2[nt].y);
                    }
                    s += __shfl_xor_sync(~0u, s, 1);
                    s += __shfl_xor_sync(~0u, s, 2);
                    if (c == 0) {
                        int jloc = w * 32 + mt * 16 + rh * 8 + gq;
                        int jg = (i + jloc) & (NN - 1);
                        g_L[((size_t)b * NN + i) * NN + jg] = s;
                        g_L[((size_t)b * NN + jg) * NN + i] = s;  // mirror
                    }
                }
            }
        }

        // Tail k=256 (single writer i<256), exact fp32 scalar
        if (i0 < 256) {
            if (tid < 64) {
                float q2 = bv[tid];
                const float* xj = xb + (size_t)(i + 256) * DD;
                #pragma unroll 8
                for (int d = 0; d < 64; d++)
                    q2 = fmaf(xi[d] * attw[d * 64 + tid], xj[d], q2);
                red[tid] = vv[tid] * fast_tanh(q2);
            }
            __syncthreads();
            if (tid == 0) {
                float s = 0.f;
                for (int o = 0; o < 64; o++) s += red[o];
                int jg = i + 256;
                g_L[((size_t)b * NN + i) * NN + jg] = s;
                g_L[((size_t)b * NN + jg) * NN + i] = s;
            }
        }
    }
}

// ---------------------------------------------------------------------------
// Kernel 2 (tiled, 512 threads): unchanged proven version.
// ---------------------------------------------------------------------------
#define ITILE 32
__global__ __launch_bounds__(512, 1) void k2_head(
    const float* __restrict__ x,
    const float* __restrict__ pwa_w, const float* __restrict__ pwa_b,
    const float* __restrict__ pwo_w, const float* __restrict__ pwo_b,
    const float* __restrict__ gamma, const float* __restrict__ beta,
    const float* __restrict__ poolw, const float* __restrict__ poolb)
{
    extern __shared__ float s2[];
    float* att = s2;                       // [32][512] (reused as hsm later)
    float* xs  = s2 + ITILE * NN;          // [512][64]
    float* agg = xs + NN * DD;             // [32][64]
    float* inv = agg + ITILE * DD;         // [32]
    float* hsm = att;

    const int itile = blockIdx.x, b = blockIdx.y;
    const int tid = threadIdx.x;
    const int wid = tid >> 5, lane = tid & 31;

    {
        const float4* Ls = (const float4*)(g_L + ((size_t)b * NN + itile * ITILE) * NN);
        float4* Ld = (float4*)att;
        for (int idx = tid; idx < ITILE * NN / 4; idx += 512) Ld[idx] = Ls[idx];
        const float4* Xs = (const float4*)(x + (size_t)b * NN * DD);
        float4* Xd = (float4*)xs;
        for (int idx = tid; idx < NN * DD / 4; idx += 512) Xd[idx] = Xs[idx];
    }
    __syncthreads();

    #pragma unroll
    for (int rr = 0; rr < 2; rr++) {
        int r = wid + rr * 16;
        float* row = att + r * NN;
        float m = -1e30f;
        #pragma unroll 4
        for (int j = lane; j < NN; j += 32) m = fmaxf(m, row[j]);
        #pragma unroll
        for (int off = 16; off; off >>= 1) m = fmaxf(m, __shfl_xor_sync(~0u, m, off));
        float ssum = 0.f;
        #pragma unroll 4
        for (int j = lane; j < NN; j += 32) {
            float e = __expf(row[j] - m);
            row[j] = e;
            ssum += e;
        }
        #pragma unroll
        for (int off = 16; off; off >>= 1) ssum += __shfl_xor_sync(~0u, ssum, off);
        if (lane == 0) inv[r] = 1.0f / ssum;
    }
    __syncthreads();

    const int d = tid & 63, ig = tid >> 6;
    float acc[4] = {0, 0, 0, 0};
    for (int j = 0; j < NN; j += 4) {
        float x0 = xs[(j + 0) * DD + d];
        float x1 = xs[(j + 1) * DD + d];
        float x2 = xs[(j + 2) * DD + d];
        float x3 = xs[(j + 3) * DD + d];
        #pragma unroll
        for (int s = 0; s < 4; s++) {
            float4 a = *(const float4*)&att[(ig * 4 + s) * NN + j];
            acc[s] = fmaf(a.x, x0, acc[s]);
            acc[s] = fmaf(a.y, x1, acc[s]);
            acc[s] = fmaf(a.z, x2, acc[s]);
            acc[s] = fmaf(a.w, x3, acc[s]);
        }
    }
    __syncthreads();
    #pragma unroll
    for (int s = 0; s < 4; s++)
        agg[(ig * 4 + s) * DD + d] = acc[s] * inv[ig * 4 + s];
    __syncthreads();

    {
        const int o = d;
        float hv[4];
        float pb = pwa_b[o] + pwo_b[o];
        #pragma unroll
        for (int s = 0; s < 4; s++) hv[s] = pb;
        #pragma unroll 8
        for (int dd = 0; dd < 64; dd++) {
            float wa = __ldg(&pwa_w[dd * 64 + o]);
            float wo = __ldg(&pwo_w[dd * 64 + o]);
            #pragma unroll
            for (int s = 0; s < 4; s++) {
                int ii = ig * 4 + s;
                hv[s] = fmaf(agg[ii * DD + dd], wa, hv[s]);
                hv[s] = fmaf(xs[(itile * ITILE + ii) * DD + dd], wo, hv[s]);
            }
        }
        const float BNS = 0.99999500003749969f;
        float gam = gamma[o] * BNS, bet = beta[o];
        const float SC = 1.0507009873554804934193349852946f;
        const float AL = 1.6732632423543772848170429916717f;
        #pragma unroll
        for (int s = 0; s < 4; s++) {
            float h = fmaf(hv[s], gam, bet);
            h = h > 0.f ? SC * h : SC * AL * expm1f(h);
            hsm[(ig * 4 + s) * DD + o] = h;
        }
    }
    __syncthreads();

    if (tid < ITILE) {
        float z = poolb[0];
        #pragma unroll 8
        for (int oo = 0; oo < 64; oo++) z = fmaf(hsm[tid * 64 + oo], poolw[oo], z);
        g_s[(size_t)b * NN + itile * ITILE + tid] = 1.0f / (1.0f + expf(-z));
    }
    {
        float4* gh = (float4*)(g_h + ((size_t)b * NN + itile * ITILE) * DD);
        const float4* hs = (const float4*)hsm;
        for (int idx = tid; idx < ITILE * DD / 4; idx += 512) gh[idx] = hs[idx];
    }
}

// ---------------------------------------------------------------------------
// Kernel 3: rank-by-count top-256 (stable: lower idx wins ties), then gather
// out[b][r] = h[b][idx_r] * score_r.  Keys unique -> ranks are a permutation.
// ---------------------------------------------------------------------------
__global__ __launch_bounds__(512) void k3_topk(float* __restrict__ out)
{
    __shared__ ull keys[NN];
    __shared__ int   idxR[KSEL];
    __shared__ float scR[KSEL];
    const int b = blockIdx.x, tid = threadIdx.x;

    float sc = g_s[(size_t)b * NN + tid];
    // key: score (positive float bits, order-preserving) | (511-idx) tiebreak
    ull mykey = ((ull)__float_as_uint(sc) << 32) | (ull)(unsigned)(511 - tid);
    keys[tid] = mykey;
    __syncthreads();

    // rank = #{keys strictly greater}; unrolled LDS.128 (2 keys per load)
    int rank = 0;
    const ulonglong2* k2p = (const ulonglong2*)keys;
    #pragma unroll 16
    for (int j = 0; j < NN / 2; j++) {
        ulonglong2 kk = k2p[j];
        rank += (kk.x > mykey) + (kk.y > mykey);
    }
    if (rank < KSEL) { idxR[rank] = tid; scR[rank] = sc; }
    __syncthreads();

    // gather: 2 threads per output row, 32 floats each (float4 x 8)
    const int r = tid >> 1, ho = (tid & 1) * 32;
    const float s = scR[r];
    const float4* hr = (const float4*)&g_h[((size_t)b * NN + idxR[r]) * DD + ho];
    float4* orow = (float4*)&out[((size_t)b * KSEL + r) * DD + ho];
    #pragma unroll
    for (int c = 0; c < 8; c++) {
        float4 v = hr[c];
        orow[c] = make_float4(v.x * s, v.y * s, v.z * s, v.w * s);
    }
}

// ---------------------------------------------------------------------------
extern "C" void kernel_launch(void* const* d_in, const int* in_sizes, int n_in,
                              void* d_out, int out_size)
{
    (void)in_sizes; (void)n_in; (void)out_size;
    const float* x      = (const float*)d_in[0];
    const float* attw   = (const float*)d_in[1];
    const float* attb   = (const float*)d_in[2];
    const float* attv   = (const float*)d_in[3];
    const float* pwa_w  = (const float*)d_in[4];
    const float* pwa_b  = (const float*)d_in[5];
    const float* pwo_w  = (const float*)d_in[6];
    const float* pwo_b  = (const float*)d_in[7];
    const float* gamma  = (const float*)d_in[8];
    const float* beta   = (const float*)d_in[9];
    const float* poolw  = (const float*)d_in[10];
    const float* poolb  = (const float*)d_in[11];

    cudaFuncSetAttribute(k1_logits, cudaFuncAttributeMaxDynamicSharedMemorySize, SMEM1);
    const int SMEM2 = (ITILE * NN + NN * DD + ITILE * DD + ITILE) * (int)sizeof(float);
    cudaFuncSetAttribute(k2_head, cudaFuncAttributeMaxDynamicSharedMemorySize, SMEM2);

    k0_cvt<<<BB * NN * 32 / 256, 256>>>(x);
    dim3 g1(NN / G, BB);
    k1_logits<<<g1, 256, SMEM1>>>(x, attw, attb, attv);
    dim3 g2(NN / ITILE, BB);
    k2_head<<<g2, 512, SMEM2>>>(x, pwa_w, pwa_b, pwo_w, pwo_b, gamma, beta, poolw, poolb);
    k3_topk<<<BB, NN>>>((float*)d_out);
}

// round 9
// speedup vs baseline: 1.9741x; 1.1711x over previous
#include <cuda_runtime.h>
#include <cuda_fp16.h>
#include <cstdint>
#include <math.h>

typedef unsigned long long ull;
typedef unsigned int u32;

#define NN 512
#define DD 64
#define BB 8
#define KSEL 256
#define G 4                   // i-values per CTA in k1

// Scratch (no allocation allowed)
__device__ float g_L[(size_t)BB * NN * NN];   // logits  8 MB
__device__ float g_h[(size_t)BB * NN * DD];   // h after selu
__device__ float g_s[(size_t)BB * NN];        // sigmoid scores
__device__ __half2 g_xhi[(size_t)BB * NN * 32];  // fp16 hi of x
__device__ __half2 g_xlo[(size_t)BB * NN * 32];  // fp16 lo residual

// Fast tanh: ex2.approx + rcp.approx + 1 Newton step. abs err ~1e-7.
__device__ __forceinline__ float fast_tanh(float x) {
    float ax = fabsf(x), t, r;
    asm("ex2.approx.f32 %0, %1;" : "=f"(t) : "f"(ax * -2.8853900817779268f));
    float u = 1.0f + t;
    asm("rcp.approx.f32 %0, %1;" : "=f"(r) : "f"(u));
    r = r * fmaf(-u, r, 2.0f);
    return copysignf((1.0f - t) * r, x);
}

__device__ __forceinline__ u32 smem_u32(const void* p) {
    u32 a;
    asm("{ .reg .u64 t; cvta.to.shared.u64 t, %1; cvt.u32.u64 %0, t; }" : "=r"(a) : "l"(p));
    return a;
}

#define LDSM4(r0, r1, r2, r3, a) \
    asm volatile("ldmatrix.sync.aligned.m8n8.x4.shared.b16 {%0,%1,%2,%3}, [%4];" \
        : "=r"(r0), "=r"(r1), "=r"(r2), "=r"(r3) : "r"(a))

__device__ __forceinline__ void mma16816(float* c, const u32* a, u32 b0, u32 b1) {
    asm volatile(
        "mma.sync.aligned.m16n8k16.row.col.f32.f16.f16.f32 "
        "{%0,%1,%2,%3}, {%4,%5,%6,%7}, {%8,%9}, {%0,%1,%2,%3};"
        : "+f"(c[0]), "+f"(c[1]), "+f"(c[2]), "+f"(c[3])
        : "r"(a[0]), "r"(a[1]), "r"(a[2]), "r"(a[3]), "r"(b0), "r"(b1));
}

// ---------------- Kernel 0: convert x to fp16 hi/lo (once) ----------------
__global__ __launch_bounds__(256) void k0_cvt(const float* __restrict__ x)
{
    int t = blockIdx.x * 256 + threadIdx.x;   // over 131072 float2
    float2 v = ((const float2*)x)[t];
    __half h0 = __float2half_rn(v.x), h1 = __float2half_rn(v.y);
    __half l0 = __float2half_rn(v.x - __half2float(h0));
    __half l1 = __float2half_rn(v.y - __half2float(h1));
    g_xhi[t] = __halves2half2(h0, h1);
    g_xlo[t] = __halves2half2(l0, l1);
}

// ---------------- Kernel 1: logits via HMMA fp16 hi/lo, G=4 i per CTA ------
// Pipelined: double-buffered B, one __syncthreads per g, tail hoisted out.
#define PITCH 144            // bytes per fp16 row of 64 (128B data + 16B pad)
#define RWIN  260            // window rows: 256 + G
#define ATILE (RWIN * PITCH) // 37440
#define BTILE (64 * PITCH)   // 9216
#define OFF_XI  0            // G*64 floats = 1024 B
#define OFF_VV  1024
#define OFF_BV  1280
#define OFF_RED 1536
#define OFF_AHI 2048
#define OFF_ALO (OFF_AHI + ATILE)
#define OFF_BB  (OFF_ALO + ATILE)            // 2 bufs x (hi+lo)
#define SMEM1   (OFF_BB + 2 * 2 * BTILE)     // 113792 bytes

__global__ __launch_bounds__(256, 2) void k1_logits(
    const float* __restrict__ x, const float* __restrict__ attw,
    const float* __restrict__ attb, const float* __restrict__ attv)
{
    extern __shared__ char smem[];
    const u32 sb = smem_u32(smem);
    const int tid = threadIdx.x, w = tid >> 5, lane = tid & 31;
    const int i0 = blockIdx.x * G, b = blockIdx.y;

    float* xia = (float*)(smem + OFF_XI);     // [G][64]
    float* vv  = (float*)(smem + OFF_VV);
    float* bv  = (float*)(smem + OFF_BV);
    float* red = (float*)(smem + OFF_RED);

    const float* xb = x + (size_t)b * NN * DD;

    if (tid < 64) { vv[tid] = attv[tid]; bv[tid] = attb[tid]; }
    xia[tid] = xb[(size_t)i0 * DD + tid];     // rows i0..i0+3 contiguous

    // A fill: copy precomputed fp16 hi/lo rows (i0..i0+259 mod 512)
    {
        const float4* xh4 = (const float4*)g_xhi;
        const float4* xl4 = (const float4*)g_xlo;
        for (int idx = tid; idx < RWIN * 8; idx += 256) {
            int r = idx >> 3, c = idx & 7;
            int grow = (i0 + r) & (NN - 1);
            size_t src = (size_t)(b * NN + grow) * 8 + c;
            u32 dst = (u32)(r * PITCH + c * 16);
            *(float4*)(smem + OFF_AHI + dst) = xh4[src];
            *(float4*)(smem + OFF_ALO + dst) = xl4[src];
        }
    }

    // B fill lambda: B[o][d] = x_i[d]*W[d][o] (fp16 hi/lo) into buffer buf
    auto fillB = [&](int g, int buf) {
        char* bhi = smem + OFF_BB + buf * 2 * BTILE;
        char* blo = bhi + BTILE;
        const float* xg = xia + g * 64;
        for (int idx = tid; idx < 64 * 64; idx += 256) {
            int d = idx >> 6, o = idx & 63;
            float wv2 = xg[d] * attw[idx];
            __half h = __float2half_rn(wv2);
            __half l = __float2half_rn(wv2 - __half2float(h));
            *(__half*)(bhi + o * PITCH + 2 * d) = h;
            *(__half*)(blo + o * PITCH + 2 * d) = l;
        }
    };
    fillB(0, 0);

    // ldmatrix lane address offsets
    const u32 aoff = (u32)((w * 32 + (lane & 15)) * PITCH + ((lane >> 4) & 1) * 16);
    const u32 boff = (u32)((((lane >> 4) & 1) * 8 + (lane & 7)) * PITCH
                           + ((lane >> 3) & 1) * 16);
    __syncthreads();

    for (int g = 0; g < G; g++) {
        const int i = i0 + g;
        const u32 ahiB = sb + OFF_AHI + aoff + (u32)(g * PITCH);
        const u32 aloB = ahiB + ATILE;
        const u32 bhiB = sb + OFF_BB + (u32)((g & 1) * 2 * BTILE) + boff;
        const u32 bloB = bhiB + BTILE;

        float acc[2][8][4];
        #pragma unroll
        for (int mt = 0; mt < 2; mt++)
            #pragma unroll
            for (int nt = 0; nt < 8; nt++)
                #pragma unroll
                for (int q = 0; q < 4; q++) acc[mt][nt][q] = 0.f;

        // ks-major: load Ahi, Bhi, Blo once; 3 MMA groups; Alo last (reuses regs)
        #pragma unroll
        for (int ks = 0; ks < 4; ks++) {
            const u32 ko = (u32)(ks * 32);
            u32 ah[2][4], bh[8][2], bl[8][2];
            LDSM4(ah[0][0], ah[0][1], ah[0][2], ah[0][3], ahiB + ko);
            LDSM4(ah[1][0], ah[1][1], ah[1][2], ah[1][3], ahiB + ko + 16 * PITCH);
            #pragma unroll
            for (int q = 0; q < 4; q++)
                LDSM4(bh[2 * q][0], bh[2 * q][1], bh[2 * q + 1][0], bh[2 * q + 1][1],
                      bhiB + ko + q * 16 * PITCH);
            #pragma unroll
            for (int q = 0; q < 4; q++)
                LDSM4(bl[2 * q][0], bl[2 * q][1], bl[2 * q + 1][0], bl[2 * q + 1][1],
                      bloB + ko + q * 16 * PITCH);
            #pragma unroll
            for (int mt = 0; mt < 2; mt++)
                #pragma unroll
                for (int nt = 0; nt < 8; nt++)
                    mma16816(acc[mt][nt], ah[mt], bh[nt][0], bh[nt][1]);
            #pragma unroll
            for (int mt = 0; mt < 2; mt++)
                #pragma unroll
                for (int nt = 0; nt < 8; nt++)
                    mma16816(acc[mt][nt], ah[mt], bl[nt][0], bl[nt][1]);
            u32 al[2][4];
            LDSM4(al[0][0], al[0][1], al[0][2], al[0][3], aloB + ko);
            LDSM4(al[1][0], al[1][1], al[1][2], al[1][3], aloB + ko + 16 * PITCH);
            #pragma unroll
            for (int mt = 0; mt < 2; mt++)
                #pragma unroll
                for (int nt = 0; nt < 8; nt++)
                    mma16816(acc[mt][nt], al[mt], bh[nt][0], bh[nt][1]);
        }

        // Prefill next B while epilogue runs (different buffer; safe, see sync)
        if (g + 1 < G) fillB(g + 1, (g + 1) & 1);

        // Epilogue: tanh + v-weighted o-reduction; lanes share j across c=lane&3
        {
            const int gq = lane >> 2, c = lane & 3;
            float2 vv2[8], bv2[8];
            #pragma unroll
            for (int nt = 0; nt < 8; nt++) {
                vv2[nt] = *(const float2*)&vv[nt * 8 + 2 * c];
                bv2[nt] = *(const float2*)&bv[nt * 8 + 2 * c];
            }
            #pragma unroll
            for (int mt = 0; mt < 2; mt++) {
                #pragma unroll
                for (int rh = 0; rh < 2; rh++) {
                    float s = 0.f;
                    #pragma unroll
                    for (int nt = 0; nt < 8; nt++) {
                        s += vv2[nt].x * fast_tanh(acc[mt][nt][2 * rh]     + bv2[nt].x);
                        s += vv2[nt].y * fast_tanh(acc[mt][nt][2 * rh + 1] + bv2[nt].y);
                    }
                    s += __shfl_xor_sync(~0u, s, 1);
                    s += __shfl_xor_sync(~0u, s, 2);
                    if (c == 0) {
                        int jloc = w * 32 + mt * 16 + rh * 8 + gq;
                        int jg = (i + jloc) & (NN - 1);
                        g_L[((size_t)b * NN + i) * NN + jg] = s;
                        g_L[((size_t)b * NN + jg) * NN + i] = s;  // mirror
                    }
                }
            }
        }
        __syncthreads();   // B(g+1) complete + all LDSM(g) done before next iter
    }

    // Tail k=256: all G i's at once; thread (g = tid>>6, o = tid&63)
    if (i0 < 256) {
        const int g = tid >> 6, o = tid & 63;
        const float* xg = xia + g * 64;
        const float* xj = xb + (size_t)(i0 + g + 256) * DD;
        float q2 = bv[o];
        #pragma unroll 8
        for (int d = 0; d < 64; d++)
            q2 = fmaf(xg[d] * attw[d * 64 + o], xj[d], q2);
        float s = vv[o] * fast_tanh(q2);
        #pragma unroll
        for (int off = 16; off; off >>= 1) s += __shfl_xor_sync(~0u, s, off);
        if (lane == 0) red[w] = s;       // warp w covers (g = w>>1, o-half = w&1)
        __syncthreads();
        if (tid < G) {
            float sv = red[2 * tid] + red[2 * tid + 1];
            int ii = i0 + tid, jg = ii + 256;
            g_L[((size_t)b * NN + ii) * NN + jg] = sv;
            g_L[((size_t)b * NN + jg) * NN + ii] = sv;
        }
    }
}

// ---------------------------------------------------------------------------
// Kernel 2 (tiled, 512 threads): unchanged proven version.
// ---------------------------------------------------------------------------
#define ITILE 32
__global__ __launch_bounds__(512, 1) void k2_head(
    const float* __restrict__ x,
    const float* __restrict__ pwa_w, const float* __restrict__ pwa_b,
    const float* __restrict__ pwo_w, const float* __restrict__ pwo_b,
    const float* __restrict__ gamma, const float* __restrict__ beta,
    const float* __restrict__ poolw, const float* __restrict__ poolb)
{
    extern __shared__ float s2[];
    float* att = s2;                       // [32][512] (reused as hsm later)
    float* xs  = s2 + ITILE * NN;          // [512][64]
    float* agg = xs + NN * DD;             // [32][64]
    float* inv = agg + ITILE * DD;         // [32]
    float* hsm = att;

    const int itile = blockIdx.x, b = blockIdx.y;
    const int tid = threadIdx.x;
    const int wid = tid >> 5, lane = tid & 31;

    {
        const float4* Ls = (const float4*)(g_L + ((size_t)b * NN + itile * ITILE) * NN);
        float4* Ld = (float4*)att;
        for (int idx = tid; idx < ITILE * NN / 4; idx += 512) Ld[idx] = Ls[idx];
        const float4* Xs = (const float4*)(x + (size_t)b * NN * DD);
        float4* Xd = (float4*)xs;
        for (int idx = tid; idx < NN * DD / 4; idx += 512) Xd[idx] = Xs[idx];
    }
    __syncthreads();

    #pragma unroll
    for (int rr = 0; rr < 2; rr++) {
        int r = wid + rr * 16;
        float* row = att + r * NN;
        float m = -1e30f;
        #pragma unroll 4
        for (int j = lane; j < NN; j += 32) m = fmaxf(m, row[j]);
        #pragma unroll
        for (int off = 16; off; off >>= 1) m = fmaxf(m, __shfl_xor_sync(~0u, m, off));
        float ssum = 0.f;
        #pragma unroll 4
        for (int j = lane; j < NN; j += 32) {
            float e = __expf(row[j] - m);
            row[j] = e;
            ssum += e;
        }
        #pragma unroll
        for (int off = 16; off; off >>= 1) ssum += __shfl_xor_sync(~0u, ssum, off);
        if (lane == 0) inv[r] = 1.0f / ssum;
    }
    __syncthreads();

    const int d = tid & 63, ig = tid >> 6;
    float acc[4] = {0, 0, 0, 0};
    for (int j = 0; j < NN; j += 4) {
        float x0 = xs[(j + 0) * DD + d];
        float x1 = xs[(j + 1) * DD + d];
        float x2 = xs[(j + 2) * DD + d];
        float x3 = xs[(j + 3) * DD + d];
        #pragma unroll
        for (int s = 0; s < 4; s++) {
            float4 a = *(const float4*)&att[(ig * 4 + s) * NN + j];
            acc[s] = fmaf(a.x, x0, acc[s]);
            acc[s] = fmaf(a.y, x1, acc[s]);
            acc[s] = fmaf(a.z, x2, acc[s]);
            acc[s] = fmaf(a.w, x3, acc[s]);
        }
    }
    __syncthreads();
    #pragma unroll
    for (int s = 0; s < 4; s++)
        agg[(ig * 4 + s) * DD + d] = acc[s] * inv[ig * 4 + s];
    __syncthreads();

    {
        const int o = d;
        float hv[4];
        float pb = pwa_b[o] + pwo_b[o];
        #pragma unroll
        for (int s = 0; s < 4; s++) hv[s] = pb;
        #pragma unroll 8
        for (int dd = 0; dd < 64; dd++) {
            float wa = __ldg(&pwa_w[dd * 64 + o]);
            float wo = __ldg(&pwo_w[dd * 64 + o]);
            #pragma unroll
            for (int s = 0; s < 4; s++) {
                int ii = ig * 4 + s;
                hv[s] = fmaf(agg[ii * DD + dd], wa, hv[s]);
                hv[s] = fmaf(xs[(itile * ITILE + ii) * DD + dd], wo, hv[s]);
            }
        }
        const float BNS = 0.99999500003749969f;
        float gam = gamma[o] * BNS, bet = beta[o];
        const float SC = 1.0507009873554804934193349852946f;
        const float AL = 1.6732632423543772848170429916717f;
        #pragma unroll
        for (int s = 0; s < 4; s++) {
            float h = fmaf(hv[s], gam, bet);
            h = h > 0.f ? SC * h : SC * AL * expm1f(h);
            hsm[(ig * 4 + s) * DD + o] = h;
        }
    }
    __syncthreads();

    if (tid < ITILE) {
        float z = poolb[0];
        #pragma unroll 8
        for (int oo = 0; oo < 64; oo++) z = fmaf(hsm[tid * 64 + oo], poolw[oo], z);
        g_s[(size_t)b * NN + itile * ITILE + tid] = 1.0f / (1.0f + expf(-z));
    }
    {
        float4* gh = (float4*)(g_h + ((size_t)b * NN + itile * ITILE) * DD);
        const float4* hs = (const float4*)hsm;
        for (int idx = tid; idx < ITILE * DD / 4; idx += 512) gh[idx] = hs[idx];
    }
}

// ---------------------------------------------------------------------------
// Kernel 3: scatter-by-rank top-256. Grid (BB, 4), 128 threads. Each thread
// owns one element, computes its rank over all 512 unique keys, and writes
// its own output row if rank < 256. Stable: lower idx wins ties.
// ---------------------------------------------------------------------------
__global__ __launch_bounds__(128) void k3_topk(float* __restrict__ out)
{
    __shared__ ull keys[NN];
    const int b = blockIdx.x, qd = blockIdx.y, tid = threadIdx.x;

    #pragma unroll
    for (int k = 0; k < 4; k++) {
        int e = k * 128 + tid;
        float sc = g_s[(size_t)b * NN + e];
        keys[e] = ((ull)__float_as_uint(sc) << 32) | (ull)(unsigned)(511 - e);
    }
    __syncthreads();

    const int e = qd * 128 + tid;
    const ull mykey = keys[e];
    int rank = 0;
    const ulonglong2* k2p = (const ulonglong2*)keys;
    #pragma unroll 16
    for (int j = 0; j < NN / 2; j++) {
        ulonglong2 kk = k2p[j];
        rank += (kk.x > mykey) + (kk.y > mykey);
    }
    if (rank < KSEL) {
        const float s = __uint_as_float((u32)(mykey >> 32));
        const float4* hr = (const float4*)&g_h[((size_t)b * NN + e) * DD];
        float4* orow = (float4*)&out[((size_t)b * KSEL + rank) * DD];
        #pragma unroll
        for (int c = 0; c < 16; c++) {
            float4 v = hr[c];
            orow[c] = make_float4(v.x * s, v.y * s, v.z * s, v.w * s);
        }
    }
}

// ---------------------------------------------------------------------------
extern "C" void kernel_launch(void* const* d_in, const int* in_sizes, int n_in,
                              void* d_out, int out_size)
{
    (void)in_sizes; (void)n_in; (void)out_size;
    const float* x      = (const float*)d_in[0];
    const float* attw   = (const float*)d_in[1];
    const float* attb   = (const float*)d_in[2];
    const float* attv   = (const float*)d_in[3];
    const float* pwa_w  = (const float*)d_in[4];
    const float* pwa_b  = (const float*)d_in[5];
    const float* pwo_w  = (const float*)d_in[6];
    const float* pwo_b  = (const float*)d_in[7];
    const float* gamma  = (const float*)d_in[8];
    const float* beta   = (const float*)d_in[9];
    const float* poolw  = (const float*)d_in[10];
    const float* poolb  = (const float*)d_in[11];

    cudaFuncSetAttribute(k1_logits, cudaFuncAttributeMaxDynamicSharedMemorySize, SMEM1);
    const int SMEM2 = (ITILE * NN + NN * DD + ITILE * DD + ITILE) * (int)sizeof(float);
    cudaFuncSetAttribute(k2_head, cudaFuncAttributeMaxDynamicSharedMemorySize, SMEM2);

    k0_cvt<<<BB * NN * 32 / 256, 256>>>(x);
    dim3 g1(NN / G, BB);
    k1_logits<<<g1, 256, SMEM1>>>(x, attw, attb, attv);
    dim3 g2(NN / ITILE, BB);
    k2_head<<<g2, 512, SMEM2>>>(x, pwa_w, pwa_b, pwo_w, pwo_b, gamma, beta, poolw, poolb);
    dim3 g3(BB, 4);
    k3_topk<<<g3, 128>>>((float*)d_out);
}

// round 10
// speedup vs baseline: 2.0665x; 1.0468x over previous
#include <cuda_runtime.h>
#include <cuda_fp16.h>
#include <cstdint>
#include <math.h>

typedef unsigned long long ull;
typedef unsigned int u32;

#define NN 512
#define DD 64
#define BB 8
#define KSEL 256
#define G 4                   // i-values per CTA in k1

// Scratch (no allocation allowed)
__device__ float g_L[(size_t)BB * NN * NN];   // logits  8 MB
__device__ float g_h[(size_t)BB * NN * DD];   // h after selu
__device__ float g_s[(size_t)BB * NN];        // sigmoid scores
__device__ __half2 g_xhi[(size_t)BB * NN * 32];  // fp16 hi of x
__device__ __half2 g_xlo[(size_t)BB * NN * 32];  // fp16 lo residual

// Fast tanh: ex2.approx + rcp.approx + 1 Newton step. abs err ~1e-7.
__device__ __forceinline__ float fast_tanh(float x) {
    float ax = fabsf(x), t, r;
    asm("ex2.approx.f32 %0, %1;" : "=f"(t) : "f"(ax * -2.8853900817779268f));
    float u = 1.0f + t;
    asm("rcp.approx.f32 %0, %1;" : "=f"(r) : "f"(u));
    r = r * fmaf(-u, r, 2.0f);
    return copysignf((1.0f - t) * r, x);
}

__device__ __forceinline__ u32 smem_u32(const void* p) {
    u32 a;
    asm("{ .reg .u64 t; cvta.to.shared.u64 t, %1; cvt.u32.u64 %0, t; }" : "=r"(a) : "l"(p));
    return a;
}

#define LDSM4(r0, r1, r2, r3, a) \
    asm volatile("ldmatrix.sync.aligned.m8n8.x4.shared.b16 {%0,%1,%2,%3}, [%4];" \
        : "=r"(r0), "=r"(r1), "=r"(r2), "=r"(r3) : "r"(a))

__device__ __forceinline__ void mma16816(float* c, const u32* a, u32 b0, u32 b1) {
    asm volatile(
        "mma.sync.aligned.m16n8k16.row.col.f32.f16.f16.f32 "
        "{%0,%1,%2,%3}, {%4,%5,%6,%7}, {%8,%9}, {%0,%1,%2,%3};"
        : "+f"(c[0]), "+f"(c[1]), "+f"(c[2]), "+f"(c[3])
        : "r"(a[0]), "r"(a[1]), "r"(a[2]), "r"(a[3]), "r"(b0), "r"(b1));
}

// ---------------- Kernel 0: convert x to fp16 hi/lo (once) ----------------
__global__ __launch_bounds__(256) void k0_cvt(const float* __restrict__ x)
{
    int t = blockIdx.x * 256 + threadIdx.x;   // over 131072 float2
    float2 v = ((const float2*)x)[t];
    __half h0 = __float2half_rn(v.x), h1 = __float2half_rn(v.y);
    __half l0 = __float2half_rn(v.x - __half2float(h0));
    __half l1 = __float2half_rn(v.y - __half2float(h1));
    g_xhi[t] = __halves2half2(h0, h1);
    g_xlo[t] = __halves2half2(l0, l1);
}

// ---------------- Kernel 1: logits via HMMA fp16 hi/lo ---------------------
// j-split: CTA = (i-group of G, j-half of 128). 3 CTAs/SM (58.5 KB smem).
#define PITCH 144            // bytes per fp16 row of 64 (128B data + 16B pad)
#define RWIN  132            // window rows: 128 + G
#define ATILE (RWIN * PITCH) // 19008
#define BTILE (64 * PITCH)   // 9216
#define OFF_XI  0            // G*64 floats = 1024 B
#define OFF_VV  1024
#define OFF_BV  1280
#define OFF_RED 1536
#define OFF_AHI 2048
#define OFF_ALO (OFF_AHI + ATILE)
#define OFF_BHI (OFF_ALO + ATILE)
#define OFF_BLO (OFF_BHI + BTILE)
#define SMEM1   (OFF_BLO + BTILE)            // 58496 bytes

__global__ __launch_bounds__(256, 3) void k1_logits(
    const float* __restrict__ x, const float* __restrict__ attw,
    const float* __restrict__ attb, const float* __restrict__ attv)
{
    extern __shared__ char smem[];
    const u32 sb = smem_u32(smem);
    const int tid = threadIdx.x, w = tid >> 5, lane = tid & 31;
    const int iblk = blockIdx.x >> 1, jh = blockIdx.x & 1;
    const int i0 = iblk * G, jbase = jh * 128, b = blockIdx.y;

    float* xia = (float*)(smem + OFF_XI);     // [G][64]
    float* vv  = (float*)(smem + OFF_VV);
    float* bv  = (float*)(smem + OFF_BV);
    float* red = (float*)(smem + OFF_RED);

    const float* xb = x + (size_t)b * NN * DD;

    if (tid < 64) { vv[tid] = attv[tid]; bv[tid] = attb[tid]; }
    xia[tid] = xb[(size_t)i0 * DD + tid];     // rows i0..i0+3 contiguous

    // A fill: fp16 hi/lo rows for j-offsets [jbase, jbase+131]
    {
        const float4* xh4 = (const float4*)g_xhi;
        const float4* xl4 = (const float4*)g_xlo;
        for (int idx = tid; idx < RWIN * 8; idx += 256) {
            int r = idx >> 3, c = idx & 7;
            int grow = (i0 + jbase + r) & (NN - 1);
            size_t src = (size_t)(b * NN + grow) * 8 + c;
            u32 dst = (u32)(r * PITCH + c * 16);
            *(float4*)(smem + OFF_AHI + dst) = xh4[src];
            *(float4*)(smem + OFF_ALO + dst) = xl4[src];
        }
    }

    // ldmatrix lane address offsets (warp owns 16 j-rows, all 64 o)
    const u32 aoff = (u32)((w * 16 + (lane & 15)) * PITCH + ((lane >> 4) & 1) * 16);
    const u32 boff = (u32)((((lane >> 4) & 1) * 8 + (lane & 7)) * PITCH
                           + ((lane >> 3) & 1) * 16);

    for (int g = 0; g < G; g++) {
        const int i = i0 + g;
        __syncthreads();   // A-fill (g=0) / prior-g B reads done

        // B fill: B[o][d] = x_i[d]*W[d][o], fp16 hi/lo (single buffer)
        {
            const float* xg = xia + g * 64;
            for (int idx = tid; idx < 64 * 64; idx += 256) {
                int d = idx >> 6, o = idx & 63;
                float wv2 = xg[d] * attw[idx];
                __half h = __float2half_rn(wv2);
                __half l = __float2half_rn(wv2 - __half2float(h));
                *(__half*)(smem + OFF_BHI + o * PITCH + 2 * d) = h;
                *(__half*)(smem + OFF_BLO + o * PITCH + 2 * d) = l;
            }
        }
        __syncthreads();   // B visible

        const u32 ahiB = sb + OFF_AHI + aoff + (u32)(g * PITCH);
        const u32 aloB = ahiB + ATILE;
        const u32 bhiB = sb + OFF_BHI + boff;
        const u32 bloB = bhiB + BTILE;

        float acc[8][4];
        #pragma unroll
        for (int nt = 0; nt < 8; nt++)
            #pragma unroll
            for (int q = 0; q < 4; q++) acc[nt][q] = 0.f;

        // ks-major; staged loads keep peak registers low
        #pragma unroll
        for (int ks = 0; ks < 4; ks++) {
            const u32 ko = (u32)(ks * 32);
            u32 ah[4], bh[8][2];
            LDSM4(ah[0], ah[1], ah[2], ah[3], ahiB + ko);
            #pragma unroll
            for (int q = 0; q < 4; q++)
                LDSM4(bh[2 * q][0], bh[2 * q][1], bh[2 * q + 1][0], bh[2 * q + 1][1],
                      bhiB + ko + q * 16 * PITCH);
            #pragma unroll
            for (int nt = 0; nt < 8; nt++)
                mma16816(acc[nt], ah, bh[nt][0], bh[nt][1]);
            {
                u32 bl[8][2];
                #pragma unroll
                for (int q = 0; q < 4; q++)
                    LDSM4(bl[2 * q][0], bl[2 * q][1], bl[2 * q + 1][0], bl[2 * q + 1][1],
                          bloB + ko + q * 16 * PITCH);
                #pragma unroll
                for (int nt = 0; nt < 8; nt++)
                    mma16816(acc[nt], ah, bl[nt][0], bl[nt][1]);
            }
            {
                u32 al[4];
                LDSM4(al[0], al[1], al[2], al[3], aloB + ko);
                #pragma unroll
                for (int nt = 0; nt < 8; nt++)
                    mma16816(acc[nt], al, bh[nt][0], bh[nt][1]);
            }
        }

        // Epilogue: tanh + v-weighted o-reduction; lanes share j across c=lane&3
        {
            const int gq = lane >> 2, c = lane & 3;
            float2 vv2[8], bv2[8];
            #pragma unroll
            for (int nt = 0; nt < 8; nt++) {
                vv2[nt] = *(const float2*)&vv[nt * 8 + 2 * c];
                bv2[nt] = *(const float2*)&bv[nt * 8 + 2 * c];
            }
            #pragma unroll
            for (int rh = 0; rh < 2; rh++) {
                float s = 0.f;
                #pragma unroll
                for (int nt = 0; nt < 8; nt++) {
                    s += vv2[nt].x * fast_tanh(acc[nt][2 * rh]     + bv2[nt].x);
                    s += vv2[nt].y * fast_tanh(acc[nt][2 * rh + 1] + bv2[nt].y);
                }
                s += __shfl_xor_sync(~0u, s, 1);
                s += __shfl_xor_sync(~0u, s, 2);
                if (c == 0) {
                    int jloc = jbase + w * 16 + rh * 8 + gq;
                    int jg = (i + jloc) & (NN - 1);
                    g_L[((size_t)b * NN + i) * NN + jg] = s;
                    g_L[((size_t)b * NN + jg) * NN + i] = s;  // mirror
                }
            }
        }
    }

    // Tail k=256: only jh==0 CTAs with i0<256; all G i's at once
    if (jh == 0 && i0 < 256) {
        const int g = tid >> 6, o = tid & 63;
        const float* xg = xia + g * 64;
        const float* xj = xb + (size_t)(i0 + g + 256) * DD;
        float q2 = bv[o];
        #pragma unroll 8
        for (int d = 0; d < 64; d++)
            q2 = fmaf(xg[d] * attw[d * 64 + o], xj[d], q2);
        float s = vv[o] * fast_tanh(q2);
        #pragma unroll
        for (int off = 16; off; off >>= 1) s += __shfl_xor_sync(~0u, s, off);
        if (lane == 0) red[w] = s;       // warp w covers (g = w>>1, o-half = w&1)
        __syncthreads();
        if (tid < G) {
            float sv = red[2 * tid] + red[2 * tid + 1];
            int ii = i0 + tid, jg = ii + 256;
            g_L[((size_t)b * NN + ii) * NN + jg] = sv;
            g_L[((size_t)b * NN + jg) * NN + ii] = sv;
        }
    }
}

// ---------------------------------------------------------------------------
// Kernel 2 (tiled, 512 threads): unchanged proven version.
// ---------------------------------------------------------------------------
#define ITILE 32
__global__ __launch_bounds__(512, 1) void k2_head(
    const float* __restrict__ x,
    const float* __restrict__ pwa_w, const float* __restrict__ pwa_b,
    const float* __restrict__ pwo_w, const float* __restrict__ pwo_b,
    const float* __restrict__ gamma, const float* __restrict__ beta,
    const float* __restrict__ poolw, const float* __restrict__ poolb)
{
    extern __shared__ float s2[];
    float* att = s2;                       // [32][512] (reused as hsm later)
    float* xs  = s2 + ITILE * NN;          // [512][64]
    float* agg = xs + NN * DD;             // [32][64]
    float* inv = agg + ITILE * DD;         // [32]
    float* hsm = att;

    const int itile = blockIdx.x, b = blockIdx.y;
    const int tid = threadIdx.x;
    const int wid = tid >> 5, lane = tid & 31;

    {
        const float4* Ls = (const float4*)(g_L + ((size_t)b * NN + itile * ITILE) * NN);
        float4* Ld = (float4*)att;
        for (int idx = tid; idx < ITILE * NN / 4; idx += 512) Ld[idx] = Ls[idx];
        const float4* Xs = (const float4*)(x + (size_t)b * NN * DD);
        float4* Xd = (float4*)xs;
        for (int idx = tid; idx < NN * DD / 4; idx += 512) Xd[idx] = Xs[idx];
    }
    __syncthreads();

    #pragma unroll
    for (int rr = 0; rr < 2; rr++) {
        int r = wid + rr * 16;
        float* row = att + r * NN;
        float m = -1e30f;
        #pragma unroll 4
        for (int j = lane; j < NN; j += 32) m = fmaxf(m, row[j]);
        #pragma unroll
        for (int off = 16; off; off >>= 1) m = fmaxf(m, __shfl_xor_sync(~0u, m, off));
        float ssum = 0.f;
        #pragma unroll 4
        for (int j = lane; j < NN; j += 32) {
            float e = __expf(row[j] - m);
            row[j] = e;
            ssum += e;
        }
        #pragma unroll
        for (int off = 16; off; off >>= 1) ssum += __shfl_xor_sync(~0u, ssum, off);
        if (lane == 0) inv[r] = 1.0f / ssum;
    }
    __syncthreads();

    const int d = tid & 63, ig = tid >> 6;
    float acc[4] = {0, 0, 0, 0};
    for (int j = 0; j < NN; j += 4) {
        float x0 = xs[(j + 0) * DD + d];
        float x1 = xs[(j + 1) * DD + d];
        float x2 = xs[(j + 2) * DD + d];
        float x3 = xs[(j + 3) * DD + d];
        #pragma unroll
        for (int s = 0; s < 4; s++) {
            float4 a = *(const float4*)&att[(ig * 4 + s) * NN + j];
            acc[s] = fmaf(a.x, x0, acc[s]);
            acc[s] = fmaf(a.y, x1, acc[s]);
            acc[s] = fmaf(a.z, x2, acc[s]);
            acc[s] = fmaf(a.w, x3, acc[s]);
        }
    }
    __syncthreads();
    #pragma unroll
    for (int s = 0; s < 4; s++)
        agg[(ig * 4 + s) * DD + d] = acc[s] * inv[ig * 4 + s];
    __syncthreads();

    {
        const int o = d;
        float hv[4];
        float pb = pwa_b[o] + pwo_b[o];
        #pragma unroll
        for (int s = 0; s < 4; s++) hv[s] = pb;
        #pragma unroll 8
        for (int dd = 0; dd < 64; dd++) {
            float wa = __ldg(&pwa_w[dd * 64 + o]);
            float wo = __ldg(&pwo_w[dd * 64 + o]);
            #pragma unroll
            for (int s = 0; s < 4; s++) {
                int ii = ig * 4 + s;
                hv[s] = fmaf(agg[ii * DD + dd], wa, hv[s]);
                hv[s] = fmaf(xs[(itile * ITILE + ii) * DD + dd], wo, hv[s]);
            }
        }
        const float BNS = 0.99999500003749969f;
        float gam = gamma[o] * BNS, bet = beta[o];
        const float SC = 1.0507009873554804934193349852946f;
        const float AL = 1.6732632423543772848170429916717f;
        #pragma unroll
        for (int s = 0; s < 4; s++) {
            float h = fmaf(hv[s], gam, bet);
            h = h > 0.f ? SC * h : SC * AL * expm1f(h);
            hsm[(ig * 4 + s) * DD + o] = h;
        }
    }
    __syncthreads();

    if (tid < ITILE) {
        float z = poolb[0];
        #pragma unroll 8
        for (int oo = 0; oo < 64; oo++) z = fmaf(hsm[tid * 64 + oo], poolw[oo], z);
        g_s[(size_t)b * NN + itile * ITILE + tid] = 1.0f / (1.0f + expf(-z));
    }
    {
        float4* gh = (float4*)(g_h + ((size_t)b * NN + itile * ITILE) * DD);
        const float4* hs = (const float4*)hsm;
        for (int idx = tid; idx < ITILE * DD / 4; idx += 512) gh[idx] = hs[idx];
    }
}

// ---------------------------------------------------------------------------
// Kernel 3: split-scan rank top-256. Grid (BB, 4), 512 threads. Each element's
// rank over 512 unique keys is computed by 4 threads (128 keys each), reduced
// in smem; rows scattered by 4 threads each. Stable: lower idx wins ties.
// ---------------------------------------------------------------------------
__global__ __launch_bounds__(512) void k3_topk(float* __restrict__ out)
{
    __shared__ ull keys[NN];
    __shared__ int pr[4][128];
    __shared__ int rankS[128];
    __shared__ float scS[128];
    const int b = blockIdx.x, qd = blockIdx.y, tid = threadIdx.x;

    {
        float sc = g_s[(size_t)b * NN + tid];
        keys[tid] = ((ull)__float_as_uint(sc) << 32) | (ull)(unsigned)(511 - tid);
    }
    __syncthreads();

    const int sub = tid >> 7, el = tid & 127;
    const int e = qd * 128 + el;
    const ull mykey = keys[e];
    int part = 0;
    const ulonglong2* k2p = (const ulonglong2*)&keys[sub * 128];
    #pragma unroll 16
    for (int j = 0; j < 64; j++) {
        ulonglong2 kk = k2p[j];
        part += (kk.x > mykey) + (kk.y > mykey);
    }
    pr[sub][el] = part;
    __syncthreads();
    if (tid < 128) {
        rankS[tid] = pr[0][tid] + pr[1][tid] + pr[2][tid] + pr[3][tid];
        scS[tid] = __uint_as_float((u32)(keys[qd * 128 + tid] >> 32));
    }
    __syncthreads();

    // scatter: 4 threads per element row (16 floats each)
    const int el2 = tid >> 2, q = tid & 3;
    const int rank = rankS[el2];
    if (rank < KSEL) {
        const float s = scS[el2];
        const float4* hr = (const float4*)&g_h[((size_t)b * NN + qd * 128 + el2) * DD + q * 16];
        float4* orow = (float4*)&out[((size_t)b * KSEL + rank) * DD + q * 16];
        #pragma unroll
        for (int c = 0; c < 4; c++) {
            float4 v = hr[c];
            orow[c] = make_float4(v.x * s, v.y * s, v.z * s, v.w * s);
        }
    }
}

// ---------------------------------------------------------------------------
extern "C" void kernel_launch(void* const* d_in, const int* in_sizes, int n_in,
                              void* d_out, int out_size)
{
    (void)in_sizes; (void)n_in; (void)out_size;
    const float* x      = (const float*)d_in[0];
    const float* attw   = (const float*)d_in[1];
    const float* attb   = (const float*)d_in[2];
    const float* attv   = (const float*)d_in[3];
    const float* pwa_w  = (const float*)d_in[4];
    const float* pwa_b  = (const float*)d_in[5];
    const float* pwo_w  = (const float*)d_in[6];
    const float* pwo_b  = (const float*)d_in[7];
    const float* gamma  = (const float*)d_in[8];
    const float* beta   = (const float*)d_in[9];
    const float* poolw  = (const float*)d_in[10];
    const float* poolb  = (const float*)d_in[11];

    cudaFuncSetAttribute(k1_logits, cudaFuncAttributeMaxDynamicSharedMemorySize, SMEM1);
    const int SMEM2 = (ITILE * NN + NN * DD + ITILE * DD + ITILE) * (int)sizeof(float);
    cudaFuncSetAttribute(k2_head, cudaFuncAttributeMaxDynamicSharedMemorySize, SMEM2);

    k0_cvt<<<BB * NN * 32 / 256, 256>>>(x);
    dim3 g1(NN / G * 2, BB);
    k1_logits<<<g1, 256, SMEM1>>>(x, attw, attb, attv);
    dim3 g2(NN / ITILE, BB);
    k2_head<<<g2, 512, SMEM2>>>(x, pwa_w, pwa_b, pwo_w, pwo_b, gamma, beta, poolw, poolb);
    dim3 g3(BB, 4);
    k3_topk<<<g3, 512>>>((float*)d_out);
}